// round 1
// baseline (speedup 1.0000x reference)
#include <cuda_runtime.h>
#include <cstdint>

#define NH    16
#define HD    128
#define SEQ   2048
#define BATCH 2
#define HID   2048

// Scratch (allocation-free: __device__ globals)
__device__ float g_Q[(size_t)BATCH * NH * SEQ * HD];   // [b,h,s,d]
__device__ float g_K[(size_t)BATCH * NH * HD * SEQ];   // [b,h,d,s]  (pre-transposed)
__device__ float g_V[(size_t)BATCH * NH * SEQ * HD];   // [b,h,s,d]
__device__ float g_O[(size_t)BATCH * SEQ * HID];       // [b,s,h*hd]

// ---------------------------------------------------------------------------
// Generic tiled fp32 GEMM + bias.
// mode 0: C[m,n] = A@W + bias           (proj -> d_out)
// mode 1: scatter QKV into g_Q / g_K(transposed) / g_V
// Tiles: 128x128x16, 256 threads, 8x8 per thread.
// ---------------------------------------------------------------------------
__global__ __launch_bounds__(256, 2) void gemm_bias_kernel(
    const float* __restrict__ A, const float* __restrict__ W,
    const float* __restrict__ bias, float* __restrict__ C,
    int M, int N, int K, int mode)
{
    __shared__ float As[16][132];   // A tile transposed: [k][m]
    __shared__ float Bs[16][132];   // W tile: [k][n]

    const int tid = threadIdx.x;
    const int tx = tid & 15, ty = tid >> 4;
    const int n0 = blockIdx.x * 128;
    const int m0 = blockIdx.y * 128;

    float acc[8][8];
#pragma unroll
    for (int i = 0; i < 8; i++)
#pragma unroll
        for (int j = 0; j < 8; j++) acc[i][j] = 0.f;

    for (int k0 = 0; k0 < K; k0 += 16) {
#pragma unroll
        for (int it = 0; it < 2; it++) {
            int f = tid + it * 256;
            int row = f >> 2;            // m-local 0..127
            int cg  = (f & 3) << 2;      // k-local 0,4,8,12
            float4 a4 = *(const float4*)(A + (size_t)(m0 + row) * K + k0 + cg);
            As[cg + 0][row] = a4.x;
            As[cg + 1][row] = a4.y;
            As[cg + 2][row] = a4.z;
            As[cg + 3][row] = a4.w;
        }
#pragma unroll
        for (int it = 0; it < 2; it++) {
            int f = tid + it * 256;
            int row = f >> 5;            // k-local 0..15
            int cg  = (f & 31) << 2;     // n-local
            *(float4*)&Bs[row][cg] =
                *(const float4*)(W + (size_t)(k0 + row) * N + n0 + cg);
        }
        __syncthreads();

#pragma unroll
        for (int kk = 0; kk < 16; kk++) {
            float a[8], b[8];
            *(float4*)&a[0] = *(float4*)&As[kk][ty * 8];
            *(float4*)&a[4] = *(float4*)&As[kk][ty * 8 + 4];
            *(float4*)&b[0] = *(float4*)&Bs[kk][tx * 8];
            *(float4*)&b[4] = *(float4*)&Bs[kk][tx * 8 + 4];
#pragma unroll
            for (int i = 0; i < 8; i++)
#pragma unroll
                for (int j = 0; j < 8; j++)
                    acc[i][j] = fmaf(a[i], b[j], acc[i][j]);
        }
        __syncthreads();
    }

    const int nbase = n0 + tx * 8;
    float bv[8];
    *(float4*)&bv[0] = *(const float4*)(bias + nbase);
    *(float4*)&bv[4] = *(const float4*)(bias + nbase + 4);

    if (mode == 0) {
#pragma unroll
        for (int i = 0; i < 8; i++) {
            int m = m0 + ty * 8 + i;
            float out[8];
#pragma unroll
            for (int j = 0; j < 8; j++) out[j] = acc[i][j] + bv[j];
            *(float4*)(C + (size_t)m * N + nbase)     = *(float4*)&out[0];
            *(float4*)(C + (size_t)m * N + nbase + 4) = *(float4*)&out[4];
        }
    } else {
        // n layout: [0,2048)=Q  [2048,4096)=K  [4096,6144)=V.
        // Thread's 8 cols sit inside one 128-wide head chunk (nbase % 8 == 0,
        // head boundaries every 128, n0 multiple of 128).
        const int part = nbase >> 11;          // 0=Q 1=K 2=V
        const int w    = nbase & 2047;
        const int h    = w >> 7;
        const int d0   = w & 127;
#pragma unroll
        for (int i = 0; i < 8; i++) {
            int m = m0 + ty * 8 + i;
            int b = m >> 11, s = m & 2047;
            int bh = b * NH + h;
            float out[8];
#pragma unroll
            for (int j = 0; j < 8; j++) out[j] = acc[i][j] + bv[j];
            if (part == 0) {
                float* dst = g_Q + ((size_t)bh * SEQ + s) * HD + d0;
                *(float4*)dst       = *(float4*)&out[0];
                *(float4*)(dst + 4) = *(float4*)&out[4];
            } else if (part == 2) {
                float* dst = g_V + ((size_t)bh * SEQ + s) * HD + d0;
                *(float4*)dst       = *(float4*)&out[0];
                *(float4*)(dst + 4) = *(float4*)&out[4];
            } else {
#pragma unroll
                for (int j = 0; j < 8; j++)
                    g_K[((size_t)bh * HD + d0 + j) * SEQ + s] = out[j];
            }
        }
    }
}

// ---------------------------------------------------------------------------
// Flash attention with causal mask + ALiBi, fp32 online softmax.
// Block: 64 q-rows; inner loop over 64-col k-tiles; 256 threads.
// smem: Qs[d=128][s=64] (T), Ks[d=128][s=64], Vs[s=64][d=128], Ps[64][64].
// ---------------------------------------------------------------------------
#define QS_STRIDE 68
#define KS_STRIDE 68
#define VS_STRIDE 132
#define PS_STRIDE 68
#define OFF_K (128 * QS_STRIDE)
#define OFF_V (OFF_K + 128 * KS_STRIDE)
#define OFF_P (OFF_V + 64 * VS_STRIDE)
#define ATT_SMEM_FLOATS (OFF_P + 64 * PS_STRIDE)

__global__ __launch_bounds__(256, 1) void attn_kernel()
{
    extern __shared__ float sm[];
    float* Qs = sm;
    float* Ks = sm + OFF_K;
    float* Vs = sm + OFF_V;
    float* Ps = sm + OFF_P;

    const int tid = threadIdx.x;
    const int tx = tid & 15, ty = tid >> 4;
    const int qt = blockIdx.x;
    const int h  = blockIdx.y;
    const int b  = blockIdx.z;
    const int bh = b * NH + h;
    const int q0 = qt * 64;
    const int r0 = ty * 4, c0 = tx * 4, co0 = tx * 8;

    const float scale = 1.f / 128.f;                      // mup: d^-1
    const float slope = exp2f(-0.5f * (float)(h + 1));    // alibi, nh=16

    const float* Qg = g_Q + ((size_t)bh * SEQ + q0) * HD;
    const float* Kg = g_K + (size_t)bh * HD * SEQ;
    const float* Vg = g_V + (size_t)bh * SEQ * HD;

    // Load Q tile transposed into Qs[d][s]
#pragma unroll
    for (int it = 0; it < 8; it++) {
        int f = tid + it * 256;
        int row = f >> 5;           // s-local 0..63
        int cg  = (f & 31) << 2;    // d
        float4 q4 = *(const float4*)(Qg + (size_t)row * HD + cg);
        Qs[(cg + 0) * QS_STRIDE + row] = q4.x;
        Qs[(cg + 1) * QS_STRIDE + row] = q4.y;
        Qs[(cg + 2) * QS_STRIDE + row] = q4.z;
        Qs[(cg + 3) * QS_STRIDE + row] = q4.w;
    }

    float o[4][8];
#pragma unroll
    for (int i = 0; i < 4; i++)
#pragma unroll
        for (int c = 0; c < 8; c++) o[i][c] = 0.f;
    float m_run[4], l_run[4];
#pragma unroll
    for (int i = 0; i < 4; i++) { m_run[i] = -1e30f; l_run[i] = 0.f; }

    for (int kt = 0; kt <= qt; kt++) {
        const int s0 = kt * 64;
        __syncthreads();   // prior tile's consumers done with Ks/Vs/Ps

        // K tile: Ks[d][s]  (global already [d][s] — coalesced)
#pragma unroll
        for (int it = 0; it < 8; it++) {
            int f = tid + it * 256;
            int row = f >> 4;           // d 0..127
            int cg  = (f & 15) << 2;    // s-local
            *(float4*)&Ks[row * KS_STRIDE + cg] =
                *(const float4*)(Kg + (size_t)row * SEQ + s0 + cg);
        }
        // V tile: Vs[s][d]
#pragma unroll
        for (int it = 0; it < 8; it++) {
            int f = tid + it * 256;
            int row = f >> 5;           // s-local 0..63
            int cg  = (f & 31) << 2;    // d
            *(float4*)&Vs[row * VS_STRIDE + cg] =
                *(const float4*)(Vg + (size_t)(s0 + row) * HD + cg);
        }
        __syncthreads();

        // S = Q @ K^T  (4x4 per thread, reduce over d=128)
        float sv[4][4];
#pragma unroll
        for (int i = 0; i < 4; i++)
#pragma unroll
            for (int j = 0; j < 4; j++) sv[i][j] = 0.f;
#pragma unroll 8
        for (int kk = 0; kk < 128; kk++) {
            float4 q4 = *(float4*)&Qs[kk * QS_STRIDE + r0];
            float4 k4 = *(float4*)&Ks[kk * KS_STRIDE + c0];
            float qa[4] = {q4.x, q4.y, q4.z, q4.w};
            float kb[4] = {k4.x, k4.y, k4.z, k4.w};
#pragma unroll
            for (int i = 0; i < 4; i++)
#pragma unroll
                for (int j = 0; j < 4; j++)
                    sv[i][j] = fmaf(qa[i], kb[j], sv[i][j]);
        }

        // scale + alibi bias + causal mask
#pragma unroll
        for (int i = 0; i < 4; i++) {
            int qr = q0 + r0 + i;
#pragma unroll
            for (int j = 0; j < 4; j++) {
                int kc = s0 + c0 + j;
                float v = fmaf(sv[i][j], scale, slope * (float)(kc - qr));
                sv[i][j] = (kc > qr) ? -1e30f : v;
            }
        }

        // online softmax (rows r0..r0+3 owned by the 16 tx-lanes of this ty)
#pragma unroll
        for (int i = 0; i < 4; i++) {
            float mx = fmaxf(fmaxf(sv[i][0], sv[i][1]), fmaxf(sv[i][2], sv[i][3]));
#pragma unroll
            for (int off = 1; off < 16; off <<= 1)
                mx = fmaxf(mx, __shfl_xor_sync(0xffffffffu, mx, off));
            float m_new = fmaxf(m_run[i], mx);
            float alpha = __expf(m_run[i] - m_new);
            float ls = 0.f;
#pragma unroll
            for (int j = 0; j < 4; j++) {
                float p = __expf(sv[i][j] - m_new);
                sv[i][j] = p;
                ls += p;
            }
#pragma unroll
            for (int off = 1; off < 16; off <<= 1)
                ls += __shfl_xor_sync(0xffffffffu, ls, off);
            l_run[i] = l_run[i] * alpha + ls;
            m_run[i] = m_new;
#pragma unroll
            for (int c = 0; c < 8; c++) o[i][c] *= alpha;
        }

        // stage P
#pragma unroll
        for (int i = 0; i < 4; i++)
            *(float4*)&Ps[(r0 + i) * PS_STRIDE + c0] =
                make_float4(sv[i][0], sv[i][1], sv[i][2], sv[i][3]);
        __syncthreads();

        // O += P @ V   (rows r0..r0+3, cols co0..co0+7)
#pragma unroll 2
        for (int j0 = 0; j0 < 64; j0 += 4) {
            float4 p4[4];
#pragma unroll
            for (int i = 0; i < 4; i++)
                p4[i] = *(float4*)&Ps[(r0 + i) * PS_STRIDE + j0];
#pragma unroll
            for (int jj = 0; jj < 4; jj++) {
                float4 va = *(float4*)&Vs[(j0 + jj) * VS_STRIDE + co0];
                float4 vb = *(float4*)&Vs[(j0 + jj) * VS_STRIDE + co0 + 4];
                float vv[8] = {va.x, va.y, va.z, va.w, vb.x, vb.y, vb.z, vb.w};
#pragma unroll
                for (int i = 0; i < 4; i++) {
                    float p = ((const float*)&p4[i])[jj];
#pragma unroll
                    for (int c = 0; c < 8; c++)
                        o[i][c] = fmaf(p, vv[c], o[i][c]);
                }
            }
        }
    }

    // normalize + write [b, s, h*HD + d]
#pragma unroll
    for (int i = 0; i < 4; i++) {
        float inv = 1.f / l_run[i];
        int qr = q0 + r0 + i;
        float* dst = g_O + ((size_t)(b * SEQ + qr)) * HID + h * HD + co0;
        *(float4*)dst       = make_float4(o[i][0] * inv, o[i][1] * inv,
                                          o[i][2] * inv, o[i][3] * inv);
        *(float4*)(dst + 4) = make_float4(o[i][4] * inv, o[i][5] * inv,
                                          o[i][6] * inv, o[i][7] * inv);
    }
}

// ---------------------------------------------------------------------------
extern "C" void kernel_launch(void* const* d_in, const int* in_sizes, int n_in,
                              void* d_out, int out_size)
{
    const float* hidden = (const float*)d_in[0];
    const float* w_qkv  = (const float*)d_in[1];
    const float* b_qkv  = (const float*)d_in[2];
    const float* w_proj = (const float*)d_in[3];
    const float* b_proj = (const float*)d_in[4];
    float* out = (float*)d_out;

    void* pO = nullptr;
    cudaGetSymbolAddress(&pO, g_O);

    cudaFuncSetAttribute(attn_kernel, cudaFuncAttributeMaxDynamicSharedMemorySize,
                         (int)(ATT_SMEM_FLOATS * sizeof(float)));

    dim3 blk(256);

    // 1) QKV GEMM + bias, scatter to Q/[K^T]/V
    dim3 g1(3 * HID / 128, (BATCH * SEQ) / 128);
    gemm_bias_kernel<<<g1, blk>>>(hidden, w_qkv, b_qkv, nullptr,
                                  BATCH * SEQ, 3 * HID, HID, 1);

    // 2) causal ALiBi flash attention
    dim3 g2(SEQ / 64, NH, BATCH);
    attn_kernel<<<g2, blk, ATT_SMEM_FLOATS * sizeof(float)>>>();

    // 3) output projection + bias -> d_out
    dim3 g3(HID / 128, (BATCH * SEQ) / 128);
    gemm_bias_kernel<<<g3, blk>>>((const float*)pO, w_proj, b_proj, out,
                                  BATCH * SEQ, HID, HID, 0);
}

// round 3
// speedup vs baseline: 1.7636x; 1.7636x over previous
#include <cuda_runtime.h>
#include <cuda_bf16.h>
#include <cstdint>

#define NH    16
#define HD    128
#define SEQ   2048
#define BATCH 2
#define HID   2048
#define MTOT  (BATCH * SEQ)   // 4096
#define GK    2048

// ---------------------------------------------------------------------------
// Scratch (__device__ globals — allocation-free)
// ---------------------------------------------------------------------------
__device__ float g_Q[(size_t)BATCH * NH * SEQ * HD];   // [b,h,s,d]
__device__ float g_K[(size_t)BATCH * NH * HD * SEQ];   // [b,h,d,s] (transposed)
__device__ float g_V[(size_t)BATCH * NH * SEQ * HD];   // [b,h,s,d]
__device__ float g_O[(size_t)BATCH * SEQ * HID];       // [b,s,h*hd]

__device__ __nv_bfloat16 g_Ah[(size_t)MTOT * HID];     // A hi (hidden or O)
__device__ __nv_bfloat16 g_Al[(size_t)MTOT * HID];     // A lo
__device__ __nv_bfloat16 g_Wqh[(size_t)3 * HID * HID]; // w_qkv^T hi  [N,K]
__device__ __nv_bfloat16 g_Wql[(size_t)3 * HID * HID]; // w_qkv^T lo
__device__ __nv_bfloat16 g_Wph[(size_t)HID * HID];     // w_proj^T hi [N,K]
__device__ __nv_bfloat16 g_Wpl[(size_t)HID * HID];     // w_proj^T lo

// ---------------------------------------------------------------------------
// helpers
// ---------------------------------------------------------------------------
__device__ __forceinline__ uint32_t smem_u32(const void* p) {
    uint32_t a;
    asm("{ .reg .u64 t; cvta.to.shared.u64 t, %1; cvt.u32.u64 %0, t; }"
        : "=r"(a) : "l"(p));
    return a;
}
__device__ __forceinline__ void cp_async16(uint32_t dst, const void* src) {
    asm volatile("cp.async.cg.shared.global [%0], [%1], 16;\n"
                 :: "r"(dst), "l"(src));
}
#define CP_COMMIT() asm volatile("cp.async.commit_group;\n" ::: "memory")
#define CP_WAIT1()  asm volatile("cp.async.wait_group 1;\n" ::: "memory")

#define LDSM_X4(r0, r1, r2, r3, addr)                                        \
    asm volatile("ldmatrix.sync.aligned.m8n8.x4.shared.b16 {%0,%1,%2,%3}, [%4];" \
                 : "=r"(r0), "=r"(r1), "=r"(r2), "=r"(r3) : "r"(addr))

#define MMA_BF16(d, a, b0, b1)                                               \
    asm volatile("mma.sync.aligned.m16n8k16.row.col.f32.bf16.bf16.f32 "      \
                 "{%0,%1,%2,%3}, {%4,%5,%6,%7}, {%8,%9}, {%0,%1,%2,%3};"     \
                 : "+f"((d)[0]), "+f"((d)[1]), "+f"((d)[2]), "+f"((d)[3])    \
                 : "r"((a)[0]), "r"((a)[1]), "r"((a)[2]), "r"((a)[3]),       \
                   "r"(b0), "r"(b1))

// ---------------------------------------------------------------------------
// Conversion kernels: fp32 -> bf16 hi/lo split
// ---------------------------------------------------------------------------
__global__ void convert_split_kernel(const float* __restrict__ in,
                                     __nv_bfloat16* __restrict__ hi,
                                     __nv_bfloat16* __restrict__ lo, int n4)
{
    int i = blockIdx.x * blockDim.x + threadIdx.x;
    if (i >= n4) return;
    float4 x = ((const float4*)in)[i];
    float v[4] = {x.x, x.y, x.z, x.w};
    __nv_bfloat16 h[4], l[4];
#pragma unroll
    for (int j = 0; j < 4; j++) {
        h[j] = __float2bfloat16_rn(v[j]);
        l[j] = __float2bfloat16_rn(v[j] - __bfloat162float(h[j]));
    }
    ushort4 hp, lp;
    hp.x = __bfloat16_as_ushort(h[0]); hp.y = __bfloat16_as_ushort(h[1]);
    hp.z = __bfloat16_as_ushort(h[2]); hp.w = __bfloat16_as_ushort(h[3]);
    lp.x = __bfloat16_as_ushort(l[0]); lp.y = __bfloat16_as_ushort(l[1]);
    lp.z = __bfloat16_as_ushort(l[2]); lp.w = __bfloat16_as_ushort(l[3]);
    ((ushort4*)hi)[i] = hp;
    ((ushort4*)lo)[i] = lp;
}

// W[K,N] fp32 -> Wt[N,K] bf16 hi/lo (tiled transpose)
__global__ void convert_w_kernel(const float* __restrict__ W,
                                 __nv_bfloat16* __restrict__ hi,
                                 __nv_bfloat16* __restrict__ lo, int K, int N)
{
    __shared__ float t[32][33];
    int n0 = blockIdx.x * 32, k0 = blockIdx.y * 32;
    int tx = threadIdx.x, ty = threadIdx.y;  // 32 x 8
#pragma unroll
    for (int r = 0; r < 4; r++)
        t[ty + r * 8][tx] = W[(size_t)(k0 + ty + r * 8) * N + n0 + tx];
    __syncthreads();
#pragma unroll
    for (int r = 0; r < 4; r++) {
        float x = t[tx][ty + r * 8];
        __nv_bfloat16 h = __float2bfloat16_rn(x);
        __nv_bfloat16 l = __float2bfloat16_rn(x - __bfloat162float(h));
        size_t idx = (size_t)(n0 + ty + r * 8) * K + k0 + tx;
        hi[idx] = h;
        lo[idx] = l;
    }
}

// ---------------------------------------------------------------------------
// mma.sync bf16-split GEMM:  C[m,n] = sum_k A[m,k]*W[k,n] + bias[n]
// A hi/lo [M,K] bf16; W hi/lo transposed [N,K] bf16.
// 3 phases (Ah*Bh, Ah*Bl, Al*Bh), fp32 register accum.
// CTA tile 128x128, 256 threads (8 warps of 64x32), K-chunk 64, cp.async x2.
// mode 0: C + bias.  mode 1: QKV scatter to g_Q / g_K(T) / g_V.
// ---------------------------------------------------------------------------
#define NCHUNK   96                 // 3 phases x 32 chunks of 64
#define ROWB     144                // padded smem row: 72 bf16 = 144 bytes
#define ATILE_B  (128 * ROWB)       // 18432
#define STAGE_B  (2 * ATILE_B)      // A + B per stage
#define GEMM_SMEM (2 * STAGE_B)     // 73728

__global__ void __launch_bounds__(256, 2) mma_gemm_kernel(
    const __nv_bfloat16* __restrict__ Ah, const __nv_bfloat16* __restrict__ Al,
    const __nv_bfloat16* __restrict__ Bh, const __nv_bfloat16* __restrict__ Bl,
    const float* __restrict__ bias, float* __restrict__ C, int N, int mode)
{
    extern __shared__ char smem[];
    const uint32_t sb = smem_u32(smem);
    const int tid = threadIdx.x;
    const int wid = tid >> 5, lane = tid & 31;
    const int n0 = blockIdx.x * 128, m0 = blockIdx.y * 128;
    const int wm = (wid & 1) * 64, wn = (wid >> 1) * 32;

    // per-thread ldmatrix byte offsets
    const uint32_t aoff = (uint32_t)(wm + (lane & 15)) * ROWB + ((lane >> 4) << 4);
    const uint32_t boff = (uint32_t)(wn + (lane & 7) + ((lane >> 4) << 3)) * ROWB
                        + (((lane >> 3) & 1) << 4);

    float acc[4][4][4];
#pragma unroll
    for (int mi = 0; mi < 4; mi++)
#pragma unroll
        for (int nj = 0; nj < 4; nj++)
#pragma unroll
            for (int d = 0; d < 4; d++) acc[mi][nj][d] = 0.f;

    auto load_chunk = [&](int c, int buf) {
        const int phase = c >> 5;
        const int kk = (c & 31) * 64;
        const __nv_bfloat16* Aa = (phase == 2) ? Al : Ah;
        const __nv_bfloat16* Bb = (phase == 1) ? Bl : Bh;
        const uint32_t sA = sb + buf * STAGE_B;
        const uint32_t sB = sA + ATILE_B;
#pragma unroll
        for (int i = 0; i < 4; i++) {
            int flat = tid + i * 256;
            int r = flat >> 3, s = (flat & 7) * 16;
            cp_async16(sA + r * ROWB + s,
                       (const char*)(Aa + (size_t)(m0 + r) * GK + kk) + s);
        }
#pragma unroll
        for (int i = 0; i < 4; i++) {
            int flat = tid + i * 256;
            int r = flat >> 3, s = (flat & 7) * 16;
            cp_async16(sB + r * ROWB + s,
                       (const char*)(Bb + (size_t)(n0 + r) * GK + kk) + s);
        }
    };

    load_chunk(0, 0); CP_COMMIT();
    load_chunk(1, 1); CP_COMMIT();

    for (int c = 0; c < NCHUNK; c++) {
        const int buf = c & 1;
        CP_WAIT1();
        __syncthreads();

        const uint32_t sA = sb + buf * STAGE_B;
        const uint32_t sB = sA + ATILE_B;
#pragma unroll
        for (int ks = 0; ks < 4; ks++) {
            uint32_t a[4][4], b[2][4];
#pragma unroll
            for (int mi = 0; mi < 4; mi++)
                LDSM_X4(a[mi][0], a[mi][1], a[mi][2], a[mi][3],
                        sA + aoff + mi * (16 * ROWB) + ks * 32);
#pragma unroll
            for (int p = 0; p < 2; p++)
                LDSM_X4(b[p][0], b[p][1], b[p][2], b[p][3],
                        sB + boff + p * (16 * ROWB) + ks * 32);
#pragma unroll
            for (int mi = 0; mi < 4; mi++)
#pragma unroll
                for (int nj = 0; nj < 4; nj++)
                    MMA_BF16(acc[mi][nj], a[mi],
                             b[nj >> 1][(nj & 1) * 2], b[nj >> 1][(nj & 1) * 2 + 1]);
        }
        __syncthreads();
        if (c + 2 < NCHUNK) load_chunk(c + 2, buf);
        CP_COMMIT();
    }

    // ---- epilogue ----
    const int g = lane >> 2, tg = lane & 3;
#pragma unroll
    for (int mi = 0; mi < 4; mi++) {
#pragma unroll
        for (int half = 0; half < 2; half++) {
            const int m = m0 + wm + mi * 16 + g + half * 8;
            const int bb = m >> 11, s = m & (SEQ - 1);
#pragma unroll
            for (int nj = 0; nj < 4; nj++) {
                const int col = n0 + wn + nj * 8 + tg * 2;
                float v0 = acc[mi][nj][half * 2 + 0] + __ldg(&bias[col]);
                float v1 = acc[mi][nj][half * 2 + 1] + __ldg(&bias[col + 1]);
                if (mode == 0) {
                    *(float2*)(C + (size_t)m * N + col) = make_float2(v0, v1);
                } else {
                    const int part = col >> 11;
                    const int h = (col >> 7) & (NH - 1);
                    const int d0 = col & (HD - 1);
                    const int bh = bb * NH + h;
                    if (part == 0) {
                        *(float2*)(g_Q + ((size_t)bh * SEQ + s) * HD + d0) =
                            make_float2(v0, v1);
                    } else if (part == 2) {
                        *(float2*)(g_V + ((size_t)bh * SEQ + s) * HD + d0) =
                            make_float2(v0, v1);
                    } else {
                        g_K[((size_t)bh * HD + d0)     * SEQ + s] = v0;
                        g_K[((size_t)bh * HD + d0 + 1) * SEQ + s] = v1;
                    }
                }
            }
        }
    }
}

// ---------------------------------------------------------------------------
// Flash attention with causal mask + ALiBi, fp32 online softmax.
// ---------------------------------------------------------------------------
#define QS_STRIDE 68
#define KS_STRIDE 68
#define VS_STRIDE 132
#define PS_STRIDE 68
#define OFF_K (128 * QS_STRIDE)
#define OFF_V (OFF_K + 128 * KS_STRIDE)
#define OFF_P (OFF_V + 64 * VS_STRIDE)
#define ATT_SMEM_FLOATS (OFF_P + 64 * PS_STRIDE)

__global__ __launch_bounds__(256, 1) void attn_kernel()
{
    extern __shared__ float sm[];
    float* Qs = sm;
    float* Ks = sm + OFF_K;
    float* Vs = sm + OFF_V;
    float* Ps = sm + OFF_P;

    const int tid = threadIdx.x;
    const int tx = tid & 15, ty = tid >> 4;
    const int qt = blockIdx.x;
    const int h  = blockIdx.y;
    const int b  = blockIdx.z;
    const int bh = b * NH + h;
    const int q0 = qt * 64;
    const int r0 = ty * 4, c0 = tx * 4, co0 = tx * 8;

    const float scale = 1.f / 128.f;
    const float slope = exp2f(-0.5f * (float)(h + 1));

    const float* Qg = g_Q + ((size_t)bh * SEQ + q0) * HD;
    const float* Kg = g_K + (size_t)bh * HD * SEQ;
    const float* Vg = g_V + (size_t)bh * SEQ * HD;

#pragma unroll
    for (int it = 0; it < 8; it++) {
        int f = tid + it * 256;
        int row = f >> 5;
        int cg  = (f & 31) << 2;
        float4 q4 = *(const float4*)(Qg + (size_t)row * HD + cg);
        Qs[(cg + 0) * QS_STRIDE + row] = q4.x;
        Qs[(cg + 1) * QS_STRIDE + row] = q4.y;
        Qs[(cg + 2) * QS_STRIDE + row] = q4.z;
        Qs[(cg + 3) * QS_STRIDE + row] = q4.w;
    }

    float o[4][8];
#pragma unroll
    for (int i = 0; i < 4; i++)
#pragma unroll
        for (int c = 0; c < 8; c++) o[i][c] = 0.f;
    float m_run[4], l_run[4];
#pragma unroll
    for (int i = 0; i < 4; i++) { m_run[i] = -1e30f; l_run[i] = 0.f; }

    for (int kt = 0; kt <= qt; kt++) {
        const int s0 = kt * 64;
        __syncthreads();

#pragma unroll
        for (int it = 0; it < 8; it++) {
            int f = tid + it * 256;
            int row = f >> 4;
            int cg  = (f & 15) << 2;
            *(float4*)&Ks[row * KS_STRIDE + cg] =
                *(const float4*)(Kg + (size_t)row * SEQ + s0 + cg);
        }
#pragma unroll
        for (int it = 0; it < 8; it++) {
            int f = tid + it * 256;
            int row = f >> 5;
            int cg  = (f & 31) << 2;
            *(float4*)&Vs[row * VS_STRIDE + cg] =
                *(const float4*)(Vg + (size_t)(s0 + row) * HD + cg);
        }
        __syncthreads();

        float sv[4][4];
#pragma unroll
        for (int i = 0; i < 4; i++)
#pragma unroll
            for (int j = 0; j < 4; j++) sv[i][j] = 0.f;
#pragma unroll 8
        for (int kk = 0; kk < 128; kk++) {
            float4 q4 = *(float4*)&Qs[kk * QS_STRIDE + r0];
            float4 k4 = *(float4*)&Ks[kk * KS_STRIDE + c0];
            float qa[4] = {q4.x, q4.y, q4.z, q4.w};
            float kb[4] = {k4.x, k4.y, k4.z, k4.w};
#pragma unroll
            for (int i = 0; i < 4; i++)
#pragma unroll
                for (int j = 0; j < 4; j++)
                    sv[i][j] = fmaf(qa[i], kb[j], sv[i][j]);
        }

#pragma unroll
        for (int i = 0; i < 4; i++) {
            int qr = q0 + r0 + i;
#pragma unroll
            for (int j = 0; j < 4; j++) {
                int kc = s0 + c0 + j;
                float v = fmaf(sv[i][j], scale, slope * (float)(kc - qr));
                sv[i][j] = (kc > qr) ? -1e30f : v;
            }
        }

#pragma unroll
        for (int i = 0; i < 4; i++) {
            float mx = fmaxf(fmaxf(sv[i][0], sv[i][1]), fmaxf(sv[i][2], sv[i][3]));
#pragma unroll
            for (int off = 1; off < 16; off <<= 1)
                mx = fmaxf(mx, __shfl_xor_sync(0xffffffffu, mx, off));
            float m_new = fmaxf(m_run[i], mx);
            float alpha = __expf(m_run[i] - m_new);
            float ls = 0.f;
#pragma unroll
            for (int j = 0; j < 4; j++) {
                float p = __expf(sv[i][j] - m_new);
                sv[i][j] = p;
                ls += p;
            }
#pragma unroll
            for (int off = 1; off < 16; off <<= 1)
                ls += __shfl_xor_sync(0xffffffffu, ls, off);
            l_run[i] = l_run[i] * alpha + ls;
            m_run[i] = m_new;
#pragma unroll
            for (int c = 0; c < 8; c++) o[i][c] *= alpha;
        }

#pragma unroll
        for (int i = 0; i < 4; i++)
            *(float4*)&Ps[(r0 + i) * PS_STRIDE + c0] =
                make_float4(sv[i][0], sv[i][1], sv[i][2], sv[i][3]);
        __syncthreads();

#pragma unroll 2
        for (int j0 = 0; j0 < 64; j0 += 4) {
            float4 p4[4];
#pragma unroll
            for (int i = 0; i < 4; i++)
                p4[i] = *(float4*)&Ps[(r0 + i) * PS_STRIDE + j0];
#pragma unroll
            for (int jj = 0; jj < 4; jj++) {
                float4 va = *(float4*)&Vs[(j0 + jj) * VS_STRIDE + co0];
                float4 vb = *(float4*)&Vs[(j0 + jj) * VS_STRIDE + co0 + 4];
                float vv[8] = {va.x, va.y, va.z, va.w, vb.x, vb.y, vb.z, vb.w};
#pragma unroll
                for (int i = 0; i < 4; i++) {
                    float p = ((const float*)&p4[i])[jj];
#pragma unroll
                    for (int c = 0; c < 8; c++)
                        o[i][c] = fmaf(p, vv[c], o[i][c]);
                }
            }
        }
    }

#pragma unroll
    for (int i = 0; i < 4; i++) {
        float inv = 1.f / l_run[i];
        int qr = q0 + r0 + i;
        float* dst = g_O + ((size_t)(b * SEQ + qr)) * HID + h * HD + co0;
        *(float4*)dst       = make_float4(o[i][0] * inv, o[i][1] * inv,
                                          o[i][2] * inv, o[i][3] * inv);
        *(float4*)(dst + 4) = make_float4(o[i][4] * inv, o[i][5] * inv,
                                          o[i][6] * inv, o[i][7] * inv);
    }
}

// ---------------------------------------------------------------------------
extern "C" void kernel_launch(void* const* d_in, const int* in_sizes, int n_in,
                              void* d_out, int out_size)
{
    const float* hidden = (const float*)d_in[0];
    const float* w_qkv  = (const float*)d_in[1];
    const float* b_qkv  = (const float*)d_in[2];
    const float* w_proj = (const float*)d_in[3];
    const float* b_proj = (const float*)d_in[4];
    float* out = (float*)d_out;

    void *pO, *pAh, *pAl, *pWqh, *pWql, *pWph, *pWpl;
    cudaGetSymbolAddress(&pO, g_O);
    cudaGetSymbolAddress(&pAh, g_Ah);  cudaGetSymbolAddress(&pAl, g_Al);
    cudaGetSymbolAddress(&pWqh, g_Wqh); cudaGetSymbolAddress(&pWql, g_Wql);
    cudaGetSymbolAddress(&pWph, g_Wph); cudaGetSymbolAddress(&pWpl, g_Wpl);

    cudaFuncSetAttribute(attn_kernel, cudaFuncAttributeMaxDynamicSharedMemorySize,
                         (int)(ATT_SMEM_FLOATS * sizeof(float)));
    cudaFuncSetAttribute(mma_gemm_kernel, cudaFuncAttributeMaxDynamicSharedMemorySize,
                         GEMM_SMEM);

    // weight conversion (transpose + split)
    convert_w_kernel<<<dim3(3 * HID / 32, HID / 32), dim3(32, 8)>>>(
        w_qkv, (__nv_bfloat16*)pWqh, (__nv_bfloat16*)pWql, HID, 3 * HID);
    convert_w_kernel<<<dim3(HID / 32, HID / 32), dim3(32, 8)>>>(
        w_proj, (__nv_bfloat16*)pWph, (__nv_bfloat16*)pWpl, HID, HID);

    // hidden -> bf16 split
    {
        int n4 = MTOT * HID / 4;
        convert_split_kernel<<<(n4 + 255) / 256, 256>>>(
            hidden, (__nv_bfloat16*)pAh, (__nv_bfloat16*)pAl, n4);
    }

    // QKV GEMM (mma.sync) -> g_Q / g_K(T) / g_V
    mma_gemm_kernel<<<dim3(3 * HID / 128, MTOT / 128), 256, GEMM_SMEM>>>(
        (const __nv_bfloat16*)pAh, (const __nv_bfloat16*)pAl,
        (const __nv_bfloat16*)pWqh, (const __nv_bfloat16*)pWql,
        b_qkv, nullptr, 3 * HID, 1);

    // attention
    attn_kernel<<<dim3(SEQ / 64, NH, BATCH), 256, ATT_SMEM_FLOATS * sizeof(float)>>>();

    // O -> bf16 split
    {
        int n4 = MTOT * HID / 4;
        convert_split_kernel<<<(n4 + 255) / 256, 256>>>(
            (const float*)pO, (__nv_bfloat16*)pAh, (__nv_bfloat16*)pAl, n4);
    }

    // proj GEMM (mma.sync) -> out
    mma_gemm_kernel<<<dim3(HID / 128, MTOT / 128), 256, GEMM_SMEM>>>(
        (const __nv_bfloat16*)pAh, (const __nv_bfloat16*)pAl,
        (const __nv_bfloat16*)pWph, (const __nv_bfloat16*)pWpl,
        b_proj, out, HID, 0);
}

// round 4
// speedup vs baseline: 2.7192x; 1.5419x over previous
#include <cuda_runtime.h>
#include <cuda_bf16.h>
#include <cstdint>

#define NH    16
#define HD    128
#define SEQ   2048
#define BATCH 2
#define HID   2048
#define MTOT  (BATCH * SEQ)   // 4096
#define GK    2048

// ---------------------------------------------------------------------------
// Scratch (__device__ globals — allocation-free)
// ---------------------------------------------------------------------------
__device__ __nv_bfloat16 g_Qh[(size_t)BATCH * NH * SEQ * HD];  // [b,h,s,d]
__device__ __nv_bfloat16 g_Ql[(size_t)BATCH * NH * SEQ * HD];
__device__ __nv_bfloat16 g_Kh[(size_t)BATCH * NH * SEQ * HD];  // [b,h,s,d]
__device__ __nv_bfloat16 g_Kl[(size_t)BATCH * NH * SEQ * HD];
__device__ __nv_bfloat16 g_Vth[(size_t)BATCH * NH * HD * SEQ]; // [b,h,d,s] (T)
__device__ __nv_bfloat16 g_Vtl[(size_t)BATCH * NH * HD * SEQ];

__device__ __nv_bfloat16 g_Ah[(size_t)MTOT * HID];     // GEMM A hi (hidden / attn-out)
__device__ __nv_bfloat16 g_Al[(size_t)MTOT * HID];     // GEMM A lo
__device__ __nv_bfloat16 g_Wqh[(size_t)3 * HID * HID]; // w_qkv^T hi  [N,K]
__device__ __nv_bfloat16 g_Wql[(size_t)3 * HID * HID];
__device__ __nv_bfloat16 g_Wph[(size_t)HID * HID];     // w_proj^T hi [N,K]
__device__ __nv_bfloat16 g_Wpl[(size_t)HID * HID];

// ---------------------------------------------------------------------------
// helpers
// ---------------------------------------------------------------------------
__device__ __forceinline__ uint32_t smem_u32(const void* p) {
    uint32_t a;
    asm("{ .reg .u64 t; cvta.to.shared.u64 t, %1; cvt.u32.u64 %0, t; }"
        : "=r"(a) : "l"(p));
    return a;
}
__device__ __forceinline__ void cp_async16(uint32_t dst, const void* src) {
    asm volatile("cp.async.cg.shared.global [%0], [%1], 16;\n"
                 :: "r"(dst), "l"(src));
}
#define CP_COMMIT() asm volatile("cp.async.commit_group;\n" ::: "memory")
#define CP_WAIT1()  asm volatile("cp.async.wait_group 1;\n" ::: "memory")
#define CP_WAIT0()  asm volatile("cp.async.wait_group 0;\n" ::: "memory")

#define LDSM_X4(r0, r1, r2, r3, addr)                                        \
    asm volatile("ldmatrix.sync.aligned.m8n8.x4.shared.b16 {%0,%1,%2,%3}, [%4];" \
                 : "=r"(r0), "=r"(r1), "=r"(r2), "=r"(r3) : "r"(addr))

#define MMA_BF16(d, a, b0, b1)                                               \
    asm volatile("mma.sync.aligned.m16n8k16.row.col.f32.bf16.bf16.f32 "      \
                 "{%0,%1,%2,%3}, {%4,%5,%6,%7}, {%8,%9}, {%0,%1,%2,%3};"     \
                 : "+f"((d)[0]), "+f"((d)[1]), "+f"((d)[2]), "+f"((d)[3])    \
                 : "r"((a)[0]), "r"((a)[1]), "r"((a)[2]), "r"((a)[3]),       \
                   "r"(b0), "r"(b1))

__device__ __forceinline__ uint32_t f2bf2(float lo, float hi) {
    __nv_bfloat162 t = __floats2bfloat162_rn(lo, hi);
    return *reinterpret_cast<uint32_t*>(&t);
}
// split (a,b) into packed bf16x2 hi and lo parts
__device__ __forceinline__ void split2(float a, float b,
                                       uint32_t& hi, uint32_t& lo) {
    float ah = __bfloat162float(__float2bfloat16_rn(a));
    float bh = __bfloat162float(__float2bfloat16_rn(b));
    hi = f2bf2(ah, bh);
    lo = f2bf2(a - ah, b - bh);
}

// ---------------------------------------------------------------------------
// Conversion kernels
// ---------------------------------------------------------------------------
__global__ void convert_split_kernel(const float* __restrict__ in,
                                     __nv_bfloat16* __restrict__ hi,
                                     __nv_bfloat16* __restrict__ lo, int n4)
{
    int i = blockIdx.x * blockDim.x + threadIdx.x;
    if (i >= n4) return;
    float4 x = ((const float4*)in)[i];
    float v[4] = {x.x, x.y, x.z, x.w};
    uint32_t h0, l0, h1, l1;
    split2(v[0], v[1], h0, l0);
    split2(v[2], v[3], h1, l1);
    ((uint2*)hi)[i] = make_uint2(h0, h1);
    ((uint2*)lo)[i] = make_uint2(l0, l1);
}

// W[K,N] fp32 -> Wt[N,K] bf16 hi/lo (tiled transpose)
__global__ void convert_w_kernel(const float* __restrict__ W,
                                 __nv_bfloat16* __restrict__ hi,
                                 __nv_bfloat16* __restrict__ lo, int K, int N)
{
    __shared__ float t[32][33];
    int n0 = blockIdx.x * 32, k0 = blockIdx.y * 32;
    int tx = threadIdx.x, ty = threadIdx.y;  // 32 x 8
#pragma unroll
    for (int r = 0; r < 4; r++)
        t[ty + r * 8][tx] = W[(size_t)(k0 + ty + r * 8) * N + n0 + tx];
    __syncthreads();
#pragma unroll
    for (int r = 0; r < 4; r++) {
        float x = t[tx][ty + r * 8];
        __nv_bfloat16 h = __float2bfloat16_rn(x);
        __nv_bfloat16 l = __float2bfloat16_rn(x - __bfloat162float(h));
        size_t idx = (size_t)(n0 + ty + r * 8) * K + k0 + tx;
        hi[idx] = h;
        lo[idx] = l;
    }
}

// ---------------------------------------------------------------------------
// mma.sync bf16-split GEMM (3 products), 128x128 tile, 256 threads.
// mode 0: C = A@W + bias (fp32 out).  mode 1: QKV -> bf16-split Q/K/V^T.
// ---------------------------------------------------------------------------
#define NCHUNK   96
#define ROWB     144
#define ATILE_B  (128 * ROWB)
#define STAGE_B  (2 * ATILE_B)
#define GEMM_SMEM (2 * STAGE_B)

__global__ void __launch_bounds__(256, 2) mma_gemm_kernel(
    const __nv_bfloat16* __restrict__ Ah, const __nv_bfloat16* __restrict__ Al,
    const __nv_bfloat16* __restrict__ Bh, const __nv_bfloat16* __restrict__ Bl,
    const float* __restrict__ bias, float* __restrict__ C, int N, int mode)
{
    extern __shared__ char smem[];
    const uint32_t sb = smem_u32(smem);
    const int tid = threadIdx.x;
    const int wid = tid >> 5, lane = tid & 31;
    const int n0 = blockIdx.x * 128, m0 = blockIdx.y * 128;
    const int wm = (wid & 1) * 64, wn = (wid >> 1) * 32;

    const uint32_t aoff = (uint32_t)(wm + (lane & 15)) * ROWB + ((lane >> 4) << 4);
    const uint32_t boff = (uint32_t)(wn + (lane & 7) + ((lane >> 4) << 3)) * ROWB
                        + (((lane >> 3) & 1) << 4);

    float acc[4][4][4];
#pragma unroll
    for (int mi = 0; mi < 4; mi++)
#pragma unroll
        for (int nj = 0; nj < 4; nj++)
#pragma unroll
            for (int d = 0; d < 4; d++) acc[mi][nj][d] = 0.f;

    auto load_chunk = [&](int c, int buf) {
        const int phase = c >> 5;
        const int kk = (c & 31) * 64;
        const __nv_bfloat16* Aa = (phase == 2) ? Al : Ah;
        const __nv_bfloat16* Bb = (phase == 1) ? Bl : Bh;
        const uint32_t sA = sb + buf * STAGE_B;
        const uint32_t sB = sA + ATILE_B;
#pragma unroll
        for (int i = 0; i < 4; i++) {
            int flat = tid + i * 256;
            int r = flat >> 3, s = (flat & 7) * 16;
            cp_async16(sA + r * ROWB + s,
                       (const char*)(Aa + (size_t)(m0 + r) * GK + kk) + s);
        }
#pragma unroll
        for (int i = 0; i < 4; i++) {
            int flat = tid + i * 256;
            int r = flat >> 3, s = (flat & 7) * 16;
            cp_async16(sB + r * ROWB + s,
                       (const char*)(Bb + (size_t)(n0 + r) * GK + kk) + s);
        }
    };

    load_chunk(0, 0); CP_COMMIT();
    load_chunk(1, 1); CP_COMMIT();

    for (int c = 0; c < NCHUNK; c++) {
        const int buf = c & 1;
        CP_WAIT1();
        __syncthreads();

        const uint32_t sA = sb + buf * STAGE_B;
        const uint32_t sB = sA + ATILE_B;
#pragma unroll
        for (int ks = 0; ks < 4; ks++) {
            uint32_t a[4][4], b[2][4];
#pragma unroll
            for (int mi = 0; mi < 4; mi++)
                LDSM_X4(a[mi][0], a[mi][1], a[mi][2], a[mi][3],
                        sA + aoff + mi * (16 * ROWB) + ks * 32);
#pragma unroll
            for (int p = 0; p < 2; p++)
                LDSM_X4(b[p][0], b[p][1], b[p][2], b[p][3],
                        sB + boff + p * (16 * ROWB) + ks * 32);
#pragma unroll
            for (int mi = 0; mi < 4; mi++)
#pragma unroll
                for (int nj = 0; nj < 4; nj++)
                    MMA_BF16(acc[mi][nj], a[mi],
                             b[nj >> 1][(nj & 1) * 2], b[nj >> 1][(nj & 1) * 2 + 1]);
        }
        __syncthreads();
        if (c + 2 < NCHUNK) load_chunk(c + 2, buf);
        CP_COMMIT();
    }

    // ---- epilogue ----
    const int g = lane >> 2, tg = lane & 3;
#pragma unroll
    for (int mi = 0; mi < 4; mi++) {
#pragma unroll
        for (int half = 0; half < 2; half++) {
            const int m = m0 + wm + mi * 16 + g + half * 8;
            const int bb = m >> 11, s = m & (SEQ - 1);
#pragma unroll
            for (int nj = 0; nj < 4; nj++) {
                const int col = n0 + wn + nj * 8 + tg * 2;
                float v0 = acc[mi][nj][half * 2 + 0] + __ldg(&bias[col]);
                float v1 = acc[mi][nj][half * 2 + 1] + __ldg(&bias[col + 1]);
                if (mode == 0) {
                    *(float2*)(C + (size_t)m * N + col) = make_float2(v0, v1);
                } else {
                    const int part = col >> 11;
                    const int h = (col >> 7) & (NH - 1);
                    const int d0 = col & (HD - 1);
                    const size_t bh = (size_t)bb * NH + h;
                    if (part == 2) {
                        // V transposed scalar stores
                        float h0 = __bfloat162float(__float2bfloat16_rn(v0));
                        float h1 = __bfloat162float(__float2bfloat16_rn(v1));
                        size_t i0 = (bh * HD + d0) * SEQ + s;
                        size_t i1 = (bh * HD + d0 + 1) * SEQ + s;
                        g_Vth[i0] = __float2bfloat16_rn(v0);
                        g_Vth[i1] = __float2bfloat16_rn(v1);
                        g_Vtl[i0] = __float2bfloat16_rn(v0 - h0);
                        g_Vtl[i1] = __float2bfloat16_rn(v1 - h1);
                    } else {
                        uint32_t hi, lo;
                        split2(v0, v1, hi, lo);
                        size_t idx = (bh * SEQ + s) * HD + d0;
                        if (part == 0) {
                            *(uint32_t*)(g_Qh + idx) = hi;
                            *(uint32_t*)(g_Ql + idx) = lo;
                        } else {
                            *(uint32_t*)(g_Kh + idx) = hi;
                            *(uint32_t*)(g_Kl + idx) = lo;
                        }
                    }
                }
            }
        }
    }
}

// ---------------------------------------------------------------------------
// Tensor-core flash attention: causal + ALiBi, bf16 hi/lo 3-product mma,
// fp32 online softmax, P fragments built in registers.
// CTA: 128 q-rows, k-tiles of 64. 8 warps (warp = 16 q-rows x full tile).
// Output written as bf16 hi/lo straight into g_Ah/g_Al (proj input).
// ---------------------------------------------------------------------------
#define QSTR 272                       // 128 bf16 + 16B pad
#define VSTR 144                       // 64 bf16 + 16B pad
#define OFF_QL (128 * QSTR)            // 34816
#define OFF_KH (2 * 128 * QSTR)        // 69632
#define OFF_KL (OFF_KH + 64 * QSTR)    // 87040
#define OFF_VH (OFF_KL + 64 * QSTR)    // 104448
#define OFF_VL (OFF_VH + 128 * VSTR)   // 122880
#define ATT_SMEM (OFF_VL + 128 * VSTR) // 141312

__global__ void __launch_bounds__(256, 1) attn_mma_kernel()
{
    extern __shared__ char smc[];
    const uint32_t sb = smem_u32(smc);
    const int tid = threadIdx.x;
    const int wid = tid >> 5, lane = tid & 31;
    const int g = lane >> 2, tg = lane & 3;
    const int qt = blockIdx.x, h = blockIdx.y, b = blockIdx.z;
    const size_t bh = (size_t)b * NH + h;
    const int q0 = qt * 128;
    const int WR = wid * 16;

    const float scale = 1.f / 128.f;
    const float slope = exp2f(-0.5f * (float)(h + 1));

    // ldmatrix offsets
    const uint32_t qbase = sb + (uint32_t)(WR + (lane & 15)) * QSTR + ((lane >> 4) << 4);
    const uint32_t kbase = sb + OFF_KH
        + (uint32_t)((lane & 7) + ((lane >> 4) << 3)) * QSTR + (((lane >> 3) & 1) << 4);
    const uint32_t vbase = sb + OFF_VH
        + (uint32_t)((lane & 7) + ((lane >> 4) << 3)) * VSTR + (((lane >> 3) & 1) << 4);

    // ---- load Q (hi/lo) ----
    {
        const __nv_bfloat16* Qh = g_Qh + (bh * SEQ + q0) * HD;
        const __nv_bfloat16* Ql = g_Ql + (bh * SEQ + q0) * HD;
#pragma unroll
        for (int i = 0; i < 8; i++) {
            int flat = tid + i * 256;
            int r = flat >> 4, cb = (flat & 15) * 16;
            cp_async16(sb + r * QSTR + cb, (const char*)(Qh + (size_t)r * HD) + cb);
        }
#pragma unroll
        for (int i = 0; i < 8; i++) {
            int flat = tid + i * 256;
            int r = flat >> 4, cb = (flat & 15) * 16;
            cp_async16(sb + OFF_QL + r * QSTR + cb, (const char*)(Ql + (size_t)r * HD) + cb);
        }
        CP_COMMIT();
    }

    float oacc[16][4];
#pragma unroll
    for (int nf = 0; nf < 16; nf++)
#pragma unroll
        for (int d = 0; d < 4; d++) oacc[nf][d] = 0.f;
    float m_run[2] = {-1e30f, -1e30f};
    float l_run[2] = {0.f, 0.f};

    const int nkt = 2 * qt + 2;
    for (int kt = 0; kt < nkt; kt++) {
        const int s0 = kt * 64;
        __syncthreads();   // prior tile consumers done with K/V smem

        // K tiles (hi/lo): 64 rows x 256B each
        {
            const __nv_bfloat16* Kh = g_Kh + (bh * SEQ + s0) * HD;
            const __nv_bfloat16* Kl = g_Kl + (bh * SEQ + s0) * HD;
#pragma unroll
            for (int i = 0; i < 4; i++) {
                int flat = tid + i * 256;
                int r = flat >> 4, cb = (flat & 15) * 16;
                cp_async16(sb + OFF_KH + r * QSTR + cb,
                           (const char*)(Kh + (size_t)r * HD) + cb);
            }
#pragma unroll
            for (int i = 0; i < 4; i++) {
                int flat = tid + i * 256;
                int r = flat >> 4, cb = (flat & 15) * 16;
                cp_async16(sb + OFF_KL + r * QSTR + cb,
                           (const char*)(Kl + (size_t)r * HD) + cb);
            }
            CP_COMMIT();
        }
        // V^T tiles (hi/lo): 128 rows x 128B each
        {
            const __nv_bfloat16* Vh = g_Vth + bh * HD * SEQ + s0;
            const __nv_bfloat16* Vl = g_Vtl + bh * HD * SEQ + s0;
#pragma unroll
            for (int i = 0; i < 4; i++) {
                int flat = tid + i * 256;
                int r = flat >> 3, cb = (flat & 7) * 16;
                cp_async16(sb + OFF_VH + r * VSTR + cb,
                           (const char*)(Vh + (size_t)r * SEQ) + cb);
            }
#pragma unroll
            for (int i = 0; i < 4; i++) {
                int flat = tid + i * 256;
                int r = flat >> 3, cb = (flat & 7) * 16;
                cp_async16(sb + OFF_VL + r * VSTR + cb,
                           (const char*)(Vl + (size_t)r * SEQ) + cb);
            }
            CP_COMMIT();
        }
        CP_WAIT1();        // K ready (Q too on first iter)
        __syncthreads();

        // ---- S = Q K^T (3 products) ----
        float sacc[8][4];
#pragma unroll
        for (int nf = 0; nf < 8; nf++)
#pragma unroll
            for (int d = 0; d < 4; d++) sacc[nf][d] = 0.f;

#pragma unroll
        for (int ks = 0; ks < 8; ks++) {
            uint32_t ah[4], al[4];
            LDSM_X4(ah[0], ah[1], ah[2], ah[3], qbase + ks * 32);
            LDSM_X4(al[0], al[1], al[2], al[3], qbase + OFF_QL + ks * 32);
#pragma unroll
            for (int j = 0; j < 4; j++) {
                uint32_t bhm[4], blm[4];
                LDSM_X4(bhm[0], bhm[1], bhm[2], bhm[3],
                        kbase + j * (16 * QSTR) + ks * 32);
                LDSM_X4(blm[0], blm[1], blm[2], blm[3],
                        kbase + (OFF_KL - OFF_KH) + j * (16 * QSTR) + ks * 32);
                MMA_BF16(sacc[2 * j],     ah, bhm[0], bhm[1]);
                MMA_BF16(sacc[2 * j],     al, bhm[0], bhm[1]);
                MMA_BF16(sacc[2 * j],     ah, blm[0], blm[1]);
                MMA_BF16(sacc[2 * j + 1], ah, bhm[2], bhm[3]);
                MMA_BF16(sacc[2 * j + 1], al, bhm[2], bhm[3]);
                MMA_BF16(sacc[2 * j + 1], ah, blm[2], blm[3]);
            }
        }

        // ---- bias + mask + online softmax ----
        const int row0 = q0 + WR + g;
        const int row1 = row0 + 8;
#pragma unroll
        for (int nf = 0; nf < 8; nf++) {
            const int cbase = s0 + nf * 8 + tg * 2;
#pragma unroll
            for (int e = 0; e < 2; e++) {
                const int col = cbase + e;
                float v0 = fmaf(sacc[nf][e], scale, slope * (float)(col - row0));
                float v1 = fmaf(sacc[nf][2 + e], scale, slope * (float)(col - row1));
                sacc[nf][e]     = (col > row0) ? -1e30f : v0;
                sacc[nf][2 + e] = (col > row1) ? -1e30f : v1;
            }
        }
#pragma unroll
        for (int half = 0; half < 2; half++) {
            float mx = -1e30f;
#pragma unroll
            for (int nf = 0; nf < 8; nf++)
                mx = fmaxf(mx, fmaxf(sacc[nf][2 * half], sacc[nf][2 * half + 1]));
            mx = fmaxf(mx, __shfl_xor_sync(0xffffffffu, mx, 1));
            mx = fmaxf(mx, __shfl_xor_sync(0xffffffffu, mx, 2));
            float m_new = fmaxf(m_run[half], mx);
            float alpha = __expf(m_run[half] - m_new);
            float ls = 0.f;
#pragma unroll
            for (int nf = 0; nf < 8; nf++) {
                float p0 = __expf(sacc[nf][2 * half] - m_new);
                float p1 = __expf(sacc[nf][2 * half + 1] - m_new);
                sacc[nf][2 * half] = p0;
                sacc[nf][2 * half + 1] = p1;
                ls += p0 + p1;
            }
            ls += __shfl_xor_sync(0xffffffffu, ls, 1);
            ls += __shfl_xor_sync(0xffffffffu, ls, 2);
            l_run[half] = l_run[half] * alpha + ls;
            m_run[half] = m_new;
#pragma unroll
            for (int nf = 0; nf < 16; nf++) {
                oacc[nf][2 * half] *= alpha;
                oacc[nf][2 * half + 1] *= alpha;
            }
        }

        CP_WAIT0();        // V ready
        __syncthreads();

        // ---- O += P V (3 products), P fragments from registers ----
#pragma unroll
        for (int ks = 0; ks < 4; ks++) {
            uint32_t aph[4], apl[4];
            {
                float f0 = sacc[2 * ks][0],     f1 = sacc[2 * ks][1];
                float f2 = sacc[2 * ks][2],     f3 = sacc[2 * ks][3];
                float f4 = sacc[2 * ks + 1][0], f5 = sacc[2 * ks + 1][1];
                float f6 = sacc[2 * ks + 1][2], f7 = sacc[2 * ks + 1][3];
                split2(f0, f1, aph[0], apl[0]);
                split2(f2, f3, aph[1], apl[1]);
                split2(f4, f5, aph[2], apl[2]);
                split2(f6, f7, aph[3], apl[3]);
            }
#pragma unroll
            for (int j = 0; j < 8; j++) {
                uint32_t bvh[4], bvl[4];
                LDSM_X4(bvh[0], bvh[1], bvh[2], bvh[3],
                        vbase + j * (16 * VSTR) + ks * 32);
                LDSM_X4(bvl[0], bvl[1], bvl[2], bvl[3],
                        vbase + (OFF_VL - OFF_VH) + j * (16 * VSTR) + ks * 32);
                MMA_BF16(oacc[2 * j],     aph, bvh[0], bvh[1]);
                MMA_BF16(oacc[2 * j],     apl, bvh[0], bvh[1]);
                MMA_BF16(oacc[2 * j],     aph, bvl[0], bvl[1]);
                MMA_BF16(oacc[2 * j + 1], aph, bvh[2], bvh[3]);
                MMA_BF16(oacc[2 * j + 1], apl, bvh[2], bvh[3]);
                MMA_BF16(oacc[2 * j + 1], aph, bvl[2], bvl[3]);
            }
        }
    }

    // ---- normalize + write bf16-split O into g_Ah/g_Al ----
    const float inv0 = 1.f / l_run[0];
    const float inv1 = 1.f / l_run[1];
#pragma unroll
    for (int nf = 0; nf < 16; nf++) {
        const int d0 = nf * 8 + tg * 2;
        {
            const int m = b * SEQ + q0 + WR + g;
            uint32_t hi, lo;
            split2(oacc[nf][0] * inv0, oacc[nf][1] * inv0, hi, lo);
            size_t idx = (size_t)m * HID + h * HD + d0;
            *(uint32_t*)(g_Ah + idx) = hi;
            *(uint32_t*)(g_Al + idx) = lo;
        }
        {
            const int m = b * SEQ + q0 + WR + g + 8;
            uint32_t hi, lo;
            split2(oacc[nf][2] * inv1, oacc[nf][3] * inv1, hi, lo);
            size_t idx = (size_t)m * HID + h * HD + d0;
            *(uint32_t*)(g_Ah + idx) = hi;
            *(uint32_t*)(g_Al + idx) = lo;
        }
    }
}

// ---------------------------------------------------------------------------
extern "C" void kernel_launch(void* const* d_in, const int* in_sizes, int n_in,
                              void* d_out, int out_size)
{
    const float* hidden = (const float*)d_in[0];
    const float* w_qkv  = (const float*)d_in[1];
    const float* b_qkv  = (const float*)d_in[2];
    const float* w_proj = (const float*)d_in[3];
    const float* b_proj = (const float*)d_in[4];
    float* out = (float*)d_out;

    void *pAh, *pAl, *pWqh, *pWql, *pWph, *pWpl;
    cudaGetSymbolAddress(&pAh, g_Ah);  cudaGetSymbolAddress(&pAl, g_Al);
    cudaGetSymbolAddress(&pWqh, g_Wqh); cudaGetSymbolAddress(&pWql, g_Wql);
    cudaGetSymbolAddress(&pWph, g_Wph); cudaGetSymbolAddress(&pWpl, g_Wpl);

    cudaFuncSetAttribute(mma_gemm_kernel, cudaFuncAttributeMaxDynamicSharedMemorySize,
                         GEMM_SMEM);
    cudaFuncSetAttribute(attn_mma_kernel, cudaFuncAttributeMaxDynamicSharedMemorySize,
                         ATT_SMEM);

    // weight conversion (transpose + split)
    convert_w_kernel<<<dim3(3 * HID / 32, HID / 32), dim3(32, 8)>>>(
        w_qkv, (__nv_bfloat16*)pWqh, (__nv_bfloat16*)pWql, HID, 3 * HID);
    convert_w_kernel<<<dim3(HID / 32, HID / 32), dim3(32, 8)>>>(
        w_proj, (__nv_bfloat16*)pWph, (__nv_bfloat16*)pWpl, HID, HID);

    // hidden -> bf16 split (GEMM A input)
    {
        int n4 = MTOT * HID / 4;
        convert_split_kernel<<<(n4 + 255) / 256, 256>>>(
            hidden, (__nv_bfloat16*)pAh, (__nv_bfloat16*)pAl, n4);
    }

    // QKV GEMM -> bf16-split Q / K / V^T
    mma_gemm_kernel<<<dim3(3 * HID / 128, MTOT / 128), 256, GEMM_SMEM>>>(
        (const __nv_bfloat16*)pAh, (const __nv_bfloat16*)pAl,
        (const __nv_bfloat16*)pWqh, (const __nv_bfloat16*)pWql,
        b_qkv, nullptr, 3 * HID, 1);

    // tensor-core flash attention -> g_Ah/g_Al (bf16 split)
    attn_mma_kernel<<<dim3(SEQ / 128, NH, BATCH), 256, ATT_SMEM>>>();

    // proj GEMM -> out
    mma_gemm_kernel<<<dim3(HID / 128, MTOT / 128), 256, GEMM_SMEM>>>(
        (const __nv_bfloat16*)pAh, (const __nv_bfloat16*)pAl,
        (const __nv_bfloat16*)pWph, (const __nv_bfloat16*)pWpl,
        b_proj, out, HID, 0);
}

// round 5
// speedup vs baseline: 2.7910x; 1.0264x over previous
#include <cuda_runtime.h>
#include <cuda_bf16.h>
#include <cstdint>

#define NH    16
#define HD    128
#define SEQ   2048
#define BATCH 2
#define HID   2048
#define MTOT  (BATCH * SEQ)   // 4096
#define GK    2048

// ---------------------------------------------------------------------------
// Scratch (__device__ globals — allocation-free)
// ---------------------------------------------------------------------------
__device__ __nv_bfloat16 g_Qh[(size_t)BATCH * NH * SEQ * HD];  // [b,h,s,d]
__device__ __nv_bfloat16 g_Ql[(size_t)BATCH * NH * SEQ * HD];
__device__ __nv_bfloat16 g_Kh[(size_t)BATCH * NH * SEQ * HD];  // [b,h,s,d]
__device__ __nv_bfloat16 g_Kl[(size_t)BATCH * NH * SEQ * HD];
__device__ __nv_bfloat16 g_Vth[(size_t)BATCH * NH * HD * SEQ]; // [b,h,d,s] (T)
__device__ __nv_bfloat16 g_Vtl[(size_t)BATCH * NH * HD * SEQ];

__device__ __nv_bfloat16 g_Ah[(size_t)MTOT * HID];     // GEMM A hi (hidden / attn-out)
__device__ __nv_bfloat16 g_Al[(size_t)MTOT * HID];     // GEMM A lo
__device__ __nv_bfloat16 g_Wqh[(size_t)3 * HID * HID]; // w_qkv^T hi  [N,K]
__device__ __nv_bfloat16 g_Wql[(size_t)3 * HID * HID];
__device__ __nv_bfloat16 g_Wph[(size_t)HID * HID];     // w_proj^T hi [N,K]
__device__ __nv_bfloat16 g_Wpl[(size_t)HID * HID];

// ---------------------------------------------------------------------------
// helpers
// ---------------------------------------------------------------------------
__device__ __forceinline__ uint32_t smem_u32(const void* p) {
    uint32_t a;
    asm("{ .reg .u64 t; cvta.to.shared.u64 t, %1; cvt.u32.u64 %0, t; }"
        : "=r"(a) : "l"(p));
    return a;
}
__device__ __forceinline__ void cp_async16(uint32_t dst, const void* src) {
    asm volatile("cp.async.cg.shared.global [%0], [%1], 16;\n"
                 :: "r"(dst), "l"(src));
}
#define CP_COMMIT() asm volatile("cp.async.commit_group;\n" ::: "memory")
#define CP_WAIT1()  asm volatile("cp.async.wait_group 1;\n" ::: "memory")
#define CP_WAIT0()  asm volatile("cp.async.wait_group 0;\n" ::: "memory")

#define LDSM_X4(r0, r1, r2, r3, addr)                                        \
    asm volatile("ldmatrix.sync.aligned.m8n8.x4.shared.b16 {%0,%1,%2,%3}, [%4];" \
                 : "=r"(r0), "=r"(r1), "=r"(r2), "=r"(r3) : "r"(addr))

#define MMA_BF16(d, a, b0, b1)                                               \
    asm volatile("mma.sync.aligned.m16n8k16.row.col.f32.bf16.bf16.f32 "      \
                 "{%0,%1,%2,%3}, {%4,%5,%6,%7}, {%8,%9}, {%0,%1,%2,%3};"     \
                 : "+f"((d)[0]), "+f"((d)[1]), "+f"((d)[2]), "+f"((d)[3])    \
                 : "r"((a)[0]), "r"((a)[1]), "r"((a)[2]), "r"((a)[3]),       \
                   "r"(b0), "r"(b1))

__device__ __forceinline__ uint32_t f2bf2(float lo, float hi) {
    __nv_bfloat162 t = __floats2bfloat162_rn(lo, hi);
    return *reinterpret_cast<uint32_t*>(&t);
}
__device__ __forceinline__ void split2(float a, float b,
                                       uint32_t& hi, uint32_t& lo) {
    float ah = __bfloat162float(__float2bfloat16_rn(a));
    float bh = __bfloat162float(__float2bfloat16_rn(b));
    hi = f2bf2(ah, bh);
    lo = f2bf2(a - ah, b - bh);
}

// ---------------------------------------------------------------------------
// Conversion kernels
// ---------------------------------------------------------------------------
__global__ void convert_split_kernel(const float* __restrict__ in,
                                     __nv_bfloat16* __restrict__ hi,
                                     __nv_bfloat16* __restrict__ lo, int n4)
{
    int i = blockIdx.x * blockDim.x + threadIdx.x;
    if (i >= n4) return;
    float4 x = ((const float4*)in)[i];
    float v[4] = {x.x, x.y, x.z, x.w};
    uint32_t h0, l0, h1, l1;
    split2(v[0], v[1], h0, l0);
    split2(v[2], v[3], h1, l1);
    ((uint2*)hi)[i] = make_uint2(h0, h1);
    ((uint2*)lo)[i] = make_uint2(l0, l1);
}

// W[K,N] fp32 -> Wt[N,K] bf16 hi/lo (tiled transpose)
__global__ void convert_w_kernel(const float* __restrict__ W,
                                 __nv_bfloat16* __restrict__ hi,
                                 __nv_bfloat16* __restrict__ lo, int K, int N)
{
    __shared__ float t[32][33];
    int n0 = blockIdx.x * 32, k0 = blockIdx.y * 32;
    int tx = threadIdx.x, ty = threadIdx.y;  // 32 x 8
#pragma unroll
    for (int r = 0; r < 4; r++)
        t[ty + r * 8][tx] = W[(size_t)(k0 + ty + r * 8) * N + n0 + tx];
    __syncthreads();
#pragma unroll
    for (int r = 0; r < 4; r++) {
        float x = t[tx][ty + r * 8];
        __nv_bfloat16 h = __float2bfloat16_rn(x);
        __nv_bfloat16 l = __float2bfloat16_rn(x - __bfloat162float(h));
        size_t idx = (size_t)(n0 + ty + r * 8) * K + k0 + tx;
        hi[idx] = h;
        lo[idx] = l;
    }
}

// ---------------------------------------------------------------------------
// mma.sync bf16-split GEMM, fused 3-product mainloop.
// Per K-chunk (32), all four tiles (Ah, Al, Bh, Bl) are resident; each
// fragment pair issues 3 products: Ah*Bh + Al*Bh + Ah*Bl.
// CTA tile 128x128, 256 threads (8 warps of 64x32), cp.async double buffer.
// mode 0: C = A@W + bias (fp32).  mode 1: QKV -> bf16-split Q/K/V^T.
// ---------------------------------------------------------------------------
#define KC       32
#define NCH      (GK / KC)           // 64
#define ROWB     80                  // 64B data + 16B pad
#define TILE_B   (128 * ROWB)        // 10240
#define STAGE_B  (4 * TILE_B)        // 40960: Ah, Al, Bh, Bl
#define GEMM_SMEM (2 * STAGE_B)      // 81920

__global__ void __launch_bounds__(256, 2) mma_gemm_kernel(
    const __nv_bfloat16* __restrict__ Ah, const __nv_bfloat16* __restrict__ Al,
    const __nv_bfloat16* __restrict__ Bh, const __nv_bfloat16* __restrict__ Bl,
    const float* __restrict__ bias, float* __restrict__ C, int N, int mode)
{
    extern __shared__ char smem[];
    const uint32_t sb = smem_u32(smem);
    const int tid = threadIdx.x;
    const int wid = tid >> 5, lane = tid & 31;
    const int n0 = blockIdx.x * 128, m0 = blockIdx.y * 128;
    const int wm = (wid & 1) * 64, wn = (wid >> 1) * 32;

    const uint32_t aoff = (uint32_t)(wm + (lane & 15)) * ROWB + ((lane >> 4) << 4);
    const uint32_t boff = (uint32_t)(wn + (lane & 7) + ((lane >> 4) << 3)) * ROWB
                        + (((lane >> 3) & 1) << 4);

    float acc[4][4][4];
#pragma unroll
    for (int mi = 0; mi < 4; mi++)
#pragma unroll
        for (int nj = 0; nj < 4; nj++)
#pragma unroll
            for (int d = 0; d < 4; d++) acc[mi][nj][d] = 0.f;

    auto load_chunk = [&](int c, int buf) {
        const int kk = c * KC;
        const uint32_t st = sb + buf * STAGE_B;
        const __nv_bfloat16* srcs[4] = {Ah, Al, Bh, Bl};
#pragma unroll
        for (int t = 0; t < 4; t++) {
            const int row0 = (t < 2) ? m0 : n0;
            const __nv_bfloat16* src = srcs[t];
            const uint32_t dst = st + t * TILE_B;
#pragma unroll
            for (int i = 0; i < 2; i++) {
                int flat = tid + i * 256;
                int r = flat >> 2, s = (flat & 3) * 16;
                cp_async16(dst + r * ROWB + s,
                           (const char*)(src + (size_t)(row0 + r) * GK + kk) + s);
            }
        }
    };

    load_chunk(0, 0); CP_COMMIT();
    load_chunk(1, 1); CP_COMMIT();

    for (int c = 0; c < NCH; c++) {
        const int buf = c & 1;
        CP_WAIT1();
        __syncthreads();

        const uint32_t sAh = sb + buf * STAGE_B;
        const uint32_t sAl = sAh + TILE_B;
        const uint32_t sBh = sAh + 2 * TILE_B;
        const uint32_t sBl = sAh + 3 * TILE_B;
#pragma unroll
        for (int ks = 0; ks < 2; ks++) {
            uint32_t bh2[2][4], bl2[2][4];
#pragma unroll
            for (int p = 0; p < 2; p++) {
                LDSM_X4(bh2[p][0], bh2[p][1], bh2[p][2], bh2[p][3],
                        sBh + boff + p * (16 * ROWB) + ks * 32);
                LDSM_X4(bl2[p][0], bl2[p][1], bl2[p][2], bl2[p][3],
                        sBl + boff + p * (16 * ROWB) + ks * 32);
            }
#pragma unroll
            for (int mi = 0; mi < 4; mi++) {
                uint32_t ah4[4], al4[4];
                LDSM_X4(ah4[0], ah4[1], ah4[2], ah4[3],
                        sAh + aoff + mi * (16 * ROWB) + ks * 32);
                LDSM_X4(al4[0], al4[1], al4[2], al4[3],
                        sAl + aoff + mi * (16 * ROWB) + ks * 32);
#pragma unroll
                for (int nj = 0; nj < 4; nj++) {
                    const int p = nj >> 1, e = (nj & 1) * 2;
                    MMA_BF16(acc[mi][nj], ah4, bh2[p][e], bh2[p][e + 1]);
                    MMA_BF16(acc[mi][nj], al4, bh2[p][e], bh2[p][e + 1]);
                    MMA_BF16(acc[mi][nj], ah4, bl2[p][e], bl2[p][e + 1]);
                }
            }
        }
        __syncthreads();
        if (c + 2 < NCH) load_chunk(c + 2, buf);
        CP_COMMIT();
    }

    // ---- epilogue ----
    const int g = lane >> 2, tg = lane & 3;
#pragma unroll
    for (int mi = 0; mi < 4; mi++) {
#pragma unroll
        for (int half = 0; half < 2; half++) {
            const int m = m0 + wm + mi * 16 + g + half * 8;
            const int bb = m >> 11, s = m & (SEQ - 1);
#pragma unroll
            for (int nj = 0; nj < 4; nj++) {
                const int col = n0 + wn + nj * 8 + tg * 2;
                float v0 = acc[mi][nj][half * 2 + 0] + __ldg(&bias[col]);
                float v1 = acc[mi][nj][half * 2 + 1] + __ldg(&bias[col + 1]);
                if (mode == 0) {
                    *(float2*)(C + (size_t)m * N + col) = make_float2(v0, v1);
                } else {
                    const int part = col >> 11;
                    const int h = (col >> 7) & (NH - 1);
                    const int d0 = col & (HD - 1);
                    const size_t bh = (size_t)bb * NH + h;
                    if (part == 2) {
                        float h0 = __bfloat162float(__float2bfloat16_rn(v0));
                        float h1 = __bfloat162float(__float2bfloat16_rn(v1));
                        size_t i0 = (bh * HD + d0) * SEQ + s;
                        size_t i1 = (bh * HD + d0 + 1) * SEQ + s;
                        g_Vth[i0] = __float2bfloat16_rn(v0);
                        g_Vth[i1] = __float2bfloat16_rn(v1);
                        g_Vtl[i0] = __float2bfloat16_rn(v0 - h0);
                        g_Vtl[i1] = __float2bfloat16_rn(v1 - h1);
                    } else {
                        uint32_t hi, lo;
                        split2(v0, v1, hi, lo);
                        size_t idx = (bh * SEQ + s) * HD + d0;
                        if (part == 0) {
                            *(uint32_t*)(g_Qh + idx) = hi;
                            *(uint32_t*)(g_Ql + idx) = lo;
                        } else {
                            *(uint32_t*)(g_Kh + idx) = hi;
                            *(uint32_t*)(g_Kl + idx) = lo;
                        }
                    }
                }
            }
        }
    }
}

// ---------------------------------------------------------------------------
// Tensor-core flash attention: causal + ALiBi, bf16 hi/lo 3-product mma,
// fp32 online softmax, P fragments built in registers.
// CTA: 128 q-rows, k-tiles of 64. 8 warps (warp = 16 q-rows x full tile).
// Output written as bf16 hi/lo straight into g_Ah/g_Al (proj input).
// ---------------------------------------------------------------------------
#define QSTR 272                       // 128 bf16 + 16B pad
#define VSTR 144                       // 64 bf16 + 16B pad
#define OFF_QL (128 * QSTR)            // 34816
#define OFF_KH (2 * 128 * QSTR)        // 69632
#define OFF_KL (OFF_KH + 64 * QSTR)    // 87040
#define OFF_VH (OFF_KL + 64 * QSTR)    // 104448
#define OFF_VL (OFF_VH + 128 * VSTR)   // 122880
#define ATT_SMEM (OFF_VL + 128 * VSTR) // 141312

__global__ void __launch_bounds__(256, 1) attn_mma_kernel()
{
    extern __shared__ char smc[];
    const uint32_t sb = smem_u32(smc);
    const int tid = threadIdx.x;
    const int wid = tid >> 5, lane = tid & 31;
    const int g = lane >> 2, tg = lane & 3;
    const int qt = blockIdx.x, h = blockIdx.y, b = blockIdx.z;
    const size_t bh = (size_t)b * NH + h;
    const int q0 = qt * 128;
    const int WR = wid * 16;

    const float scale = 1.f / 128.f;
    const float slope = exp2f(-0.5f * (float)(h + 1));

    const uint32_t qbase = sb + (uint32_t)(WR + (lane & 15)) * QSTR + ((lane >> 4) << 4);
    const uint32_t kbase = sb + OFF_KH
        + (uint32_t)((lane & 7) + ((lane >> 4) << 3)) * QSTR + (((lane >> 3) & 1) << 4);
    const uint32_t vbase = sb + OFF_VH
        + (uint32_t)((lane & 7) + ((lane >> 4) << 3)) * VSTR + (((lane >> 3) & 1) << 4);

    // ---- load Q (hi/lo) ----
    {
        const __nv_bfloat16* Qh = g_Qh + (bh * SEQ + q0) * HD;
        const __nv_bfloat16* Ql = g_Ql + (bh * SEQ + q0) * HD;
#pragma unroll
        for (int i = 0; i < 8; i++) {
            int flat = tid + i * 256;
            int r = flat >> 4, cb = (flat & 15) * 16;
            cp_async16(sb + r * QSTR + cb, (const char*)(Qh + (size_t)r * HD) + cb);
        }
#pragma unroll
        for (int i = 0; i < 8; i++) {
            int flat = tid + i * 256;
            int r = flat >> 4, cb = (flat & 15) * 16;
            cp_async16(sb + OFF_QL + r * QSTR + cb, (const char*)(Ql + (size_t)r * HD) + cb);
        }
        CP_COMMIT();
    }

    float oacc[16][4];
#pragma unroll
    for (int nf = 0; nf < 16; nf++)
#pragma unroll
        for (int d = 0; d < 4; d++) oacc[nf][d] = 0.f;
    float m_run[2] = {-1e30f, -1e30f};
    float l_run[2] = {0.f, 0.f};

    const int nkt = 2 * qt + 2;
    for (int kt = 0; kt < nkt; kt++) {
        const int s0 = kt * 64;
        __syncthreads();

        {
            const __nv_bfloat16* Kh = g_Kh + (bh * SEQ + s0) * HD;
            const __nv_bfloat16* Kl = g_Kl + (bh * SEQ + s0) * HD;
#pragma unroll
            for (int i = 0; i < 4; i++) {
                int flat = tid + i * 256;
                int r = flat >> 4, cb = (flat & 15) * 16;
                cp_async16(sb + OFF_KH + r * QSTR + cb,
                           (const char*)(Kh + (size_t)r * HD) + cb);
            }
#pragma unroll
            for (int i = 0; i < 4; i++) {
                int flat = tid + i * 256;
                int r = flat >> 4, cb = (flat & 15) * 16;
                cp_async16(sb + OFF_KL + r * QSTR + cb,
                           (const char*)(Kl + (size_t)r * HD) + cb);
            }
            CP_COMMIT();
        }
        {
            const __nv_bfloat16* Vh = g_Vth + bh * HD * SEQ + s0;
            const __nv_bfloat16* Vl = g_Vtl + bh * HD * SEQ + s0;
#pragma unroll
            for (int i = 0; i < 4; i++) {
                int flat = tid + i * 256;
                int r = flat >> 3, cb = (flat & 7) * 16;
                cp_async16(sb + OFF_VH + r * VSTR + cb,
                           (const char*)(Vh + (size_t)r * SEQ) + cb);
            }
#pragma unroll
            for (int i = 0; i < 4; i++) {
                int flat = tid + i * 256;
                int r = flat >> 3, cb = (flat & 7) * 16;
                cp_async16(sb + OFF_VL + r * VSTR + cb,
                           (const char*)(Vl + (size_t)r * SEQ) + cb);
            }
            CP_COMMIT();
        }
        CP_WAIT1();
        __syncthreads();

        // ---- S = Q K^T (3 products) ----
        float sacc[8][4];
#pragma unroll
        for (int nf = 0; nf < 8; nf++)
#pragma unroll
            for (int d = 0; d < 4; d++) sacc[nf][d] = 0.f;

#pragma unroll
        for (int ks = 0; ks < 8; ks++) {
            uint32_t ah[4], al[4];
            LDSM_X4(ah[0], ah[1], ah[2], ah[3], qbase + ks * 32);
            LDSM_X4(al[0], al[1], al[2], al[3], qbase + OFF_QL + ks * 32);
#pragma unroll
            for (int j = 0; j < 4; j++) {
                uint32_t bhm[4], blm[4];
                LDSM_X4(bhm[0], bhm[1], bhm[2], bhm[3],
                        kbase + j * (16 * QSTR) + ks * 32);
                LDSM_X4(blm[0], blm[1], blm[2], blm[3],
                        kbase + (OFF_KL - OFF_KH) + j * (16 * QSTR) + ks * 32);
                MMA_BF16(sacc[2 * j],     ah, bhm[0], bhm[1]);
                MMA_BF16(sacc[2 * j],     al, bhm[0], bhm[1]);
                MMA_BF16(sacc[2 * j],     ah, blm[0], blm[1]);
                MMA_BF16(sacc[2 * j + 1], ah, bhm[2], bhm[3]);
                MMA_BF16(sacc[2 * j + 1], al, bhm[2], bhm[3]);
                MMA_BF16(sacc[2 * j + 1], ah, blm[2], blm[3]);
            }
        }

        // ---- bias + mask + online softmax ----
        const int row0 = q0 + WR + g;
        const int row1 = row0 + 8;
#pragma unroll
        for (int nf = 0; nf < 8; nf++) {
            const int cbase = s0 + nf * 8 + tg * 2;
#pragma unroll
            for (int e = 0; e < 2; e++) {
                const int col = cbase + e;
                float v0 = fmaf(sacc[nf][e], scale, slope * (float)(col - row0));
                float v1 = fmaf(sacc[nf][2 + e], scale, slope * (float)(col - row1));
                sacc[nf][e]     = (col > row0) ? -1e30f : v0;
                sacc[nf][2 + e] = (col > row1) ? -1e30f : v1;
            }
        }
#pragma unroll
        for (int half = 0; half < 2; half++) {
            float mx = -1e30f;
#pragma unroll
            for (int nf = 0; nf < 8; nf++)
                mx = fmaxf(mx, fmaxf(sacc[nf][2 * half], sacc[nf][2 * half + 1]));
            mx = fmaxf(mx, __shfl_xor_sync(0xffffffffu, mx, 1));
            mx = fmaxf(mx, __shfl_xor_sync(0xffffffffu, mx, 2));
            float m_new = fmaxf(m_run[half], mx);
            float alpha = __expf(m_run[half] - m_new);
            float ls = 0.f;
#pragma unroll
            for (int nf = 0; nf < 8; nf++) {
                float p0 = __expf(sacc[nf][2 * half] - m_new);
                float p1 = __expf(sacc[nf][2 * half + 1] - m_new);
                sacc[nf][2 * half] = p0;
                sacc[nf][2 * half + 1] = p1;
                ls += p0 + p1;
            }
            ls += __shfl_xor_sync(0xffffffffu, ls, 1);
            ls += __shfl_xor_sync(0xffffffffu, ls, 2);
            l_run[half] = l_run[half] * alpha + ls;
            m_run[half] = m_new;
#pragma unroll
            for (int nf = 0; nf < 16; nf++) {
                oacc[nf][2 * half] *= alpha;
                oacc[nf][2 * half + 1] *= alpha;
            }
        }

        CP_WAIT0();
        __syncthreads();

        // ---- O += P V (3 products), P fragments from registers ----
#pragma unroll
        for (int ks = 0; ks < 4; ks++) {
            uint32_t aph[4], apl[4];
            {
                split2(sacc[2 * ks][0],     sacc[2 * ks][1],     aph[0], apl[0]);
                split2(sacc[2 * ks][2],     sacc[2 * ks][3],     aph[1], apl[1]);
                split2(sacc[2 * ks + 1][0], sacc[2 * ks + 1][1], aph[2], apl[2]);
                split2(sacc[2 * ks + 1][2], sacc[2 * ks + 1][3], aph[3], apl[3]);
            }
#pragma unroll
            for (int j = 0; j < 8; j++) {
                uint32_t bvh[4], bvl[4];
                LDSM_X4(bvh[0], bvh[1], bvh[2], bvh[3],
                        vbase + j * (16 * VSTR) + ks * 32);
                LDSM_X4(bvl[0], bvl[1], bvl[2], bvl[3],
                        vbase + (OFF_VL - OFF_VH) + j * (16 * VSTR) + ks * 32);
                MMA_BF16(oacc[2 * j],     aph, bvh[0], bvh[1]);
                MMA_BF16(oacc[2 * j],     apl, bvh[0], bvh[1]);
                MMA_BF16(oacc[2 * j],     aph, bvl[0], bvl[1]);
                MMA_BF16(oacc[2 * j + 1], aph, bvh[2], bvh[3]);
                MMA_BF16(oacc[2 * j + 1], apl, bvh[2], bvh[3]);
                MMA_BF16(oacc[2 * j + 1], aph, bvl[2], bvl[3]);
            }
        }
    }

    // ---- normalize + write bf16-split O into g_Ah/g_Al ----
    const float inv0 = 1.f / l_run[0];
    const float inv1 = 1.f / l_run[1];
#pragma unroll
    for (int nf = 0; nf < 16; nf++) {
        const int d0 = nf * 8 + tg * 2;
        {
            const int m = b * SEQ + q0 + WR + g;
            uint32_t hi, lo;
            split2(oacc[nf][0] * inv0, oacc[nf][1] * inv0, hi, lo);
            size_t idx = (size_t)m * HID + h * HD + d0;
            *(uint32_t*)(g_Ah + idx) = hi;
            *(uint32_t*)(g_Al + idx) = lo;
        }
        {
            const int m = b * SEQ + q0 + WR + g + 8;
            uint32_t hi, lo;
            split2(oacc[nf][2] * inv1, oacc[nf][3] * inv1, hi, lo);
            size_t idx = (size_t)m * HID + h * HD + d0;
            *(uint32_t*)(g_Ah + idx) = hi;
            *(uint32_t*)(g_Al + idx) = lo;
        }
    }
}

// ---------------------------------------------------------------------------
extern "C" void kernel_launch(void* const* d_in, const int* in_sizes, int n_in,
                              void* d_out, int out_size)
{
    const float* hidden = (const float*)d_in[0];
    const float* w_qkv  = (const float*)d_in[1];
    const float* b_qkv  = (const float*)d_in[2];
    const float* w_proj = (const float*)d_in[3];
    const float* b_proj = (const float*)d_in[4];
    float* out = (float*)d_out;

    void *pAh, *pAl, *pWqh, *pWql, *pWph, *pWpl;
    cudaGetSymbolAddress(&pAh, g_Ah);  cudaGetSymbolAddress(&pAl, g_Al);
    cudaGetSymbolAddress(&pWqh, g_Wqh); cudaGetSymbolAddress(&pWql, g_Wql);
    cudaGetSymbolAddress(&pWph, g_Wph); cudaGetSymbolAddress(&pWpl, g_Wpl);

    cudaFuncSetAttribute(mma_gemm_kernel, cudaFuncAttributeMaxDynamicSharedMemorySize,
                         GEMM_SMEM);
    cudaFuncSetAttribute(attn_mma_kernel, cudaFuncAttributeMaxDynamicSharedMemorySize,
                         ATT_SMEM);

    // weight conversion (transpose + split)
    convert_w_kernel<<<dim3(3 * HID / 32, HID / 32), dim3(32, 8)>>>(
        w_qkv, (__nv_bfloat16*)pWqh, (__nv_bfloat16*)pWql, HID, 3 * HID);
    convert_w_kernel<<<dim3(HID / 32, HID / 32), dim3(32, 8)>>>(
        w_proj, (__nv_bfloat16*)pWph, (__nv_bfloat16*)pWpl, HID, HID);

    // hidden -> bf16 split (GEMM A input)
    {
        int n4 = MTOT * HID / 4;
        convert_split_kernel<<<(n4 + 255) / 256, 256>>>(
            hidden, (__nv_bfloat16*)pAh, (__nv_bfloat16*)pAl, n4);
    }

    // QKV GEMM -> bf16-split Q / K / V^T
    mma_gemm_kernel<<<dim3(3 * HID / 128, MTOT / 128), 256, GEMM_SMEM>>>(
        (const __nv_bfloat16*)pAh, (const __nv_bfloat16*)pAl,
        (const __nv_bfloat16*)pWqh, (const __nv_bfloat16*)pWql,
        b_qkv, nullptr, 3 * HID, 1);

    // tensor-core flash attention -> g_Ah/g_Al (bf16 split)
    attn_mma_kernel<<<dim3(SEQ / 128, NH, BATCH), 256, ATT_SMEM>>>();

    // proj GEMM -> out
    mma_gemm_kernel<<<dim3(HID / 128, MTOT / 128), 256, GEMM_SMEM>>>(
        (const __nv_bfloat16*)pAh, (const __nv_bfloat16*)pAl,
        (const __nv_bfloat16*)pWph, (const __nv_bfloat16*)pWpl,
        b_proj, out, HID, 0);
}

// round 6
// speedup vs baseline: 3.7757x; 1.3528x over previous
#include <cuda_runtime.h>
#include <cuda_fp16.h>
#include <cstdint>

#define NH    16
#define HD    128
#define SEQ   2048
#define BATCH 2
#define HID   2048
#define MTOT  (BATCH * SEQ)   // 4096
#define GK    2048

// ---------------------------------------------------------------------------
// Scratch (__device__ globals — allocation-free)
// ---------------------------------------------------------------------------
__device__ __half g_Qh[(size_t)BATCH * NH * SEQ * HD];  // Q hi [b,h,s,d]
__device__ __half g_Ql[(size_t)BATCH * NH * SEQ * HD];  // Q lo
__device__ __half g_K [(size_t)BATCH * NH * SEQ * HD];  // K single [b,h,s,d]
__device__ __half g_Vt[(size_t)BATCH * NH * HD * SEQ];  // V single [b,h,d,s]

__device__ __half g_Ah[(size_t)MTOT * HID];      // GEMM A hi (hidden / attn-out)
__device__ __half g_Al[(size_t)MTOT * HID];      // GEMM A lo
__device__ __half g_Wq[(size_t)3 * HID * HID];   // w_qkv^T fp16 [N,K]
__device__ __half g_Wp[(size_t)HID * HID];       // w_proj^T fp16 [N,K]

// ---------------------------------------------------------------------------
// helpers
// ---------------------------------------------------------------------------
__device__ __forceinline__ uint32_t smem_u32(const void* p) {
    uint32_t a;
    asm("{ .reg .u64 t; cvta.to.shared.u64 t, %1; cvt.u32.u64 %0, t; }"
        : "=r"(a) : "l"(p));
    return a;
}
__device__ __forceinline__ void cp_async16(uint32_t dst, const void* src) {
    asm volatile("cp.async.cg.shared.global [%0], [%1], 16;\n"
                 :: "r"(dst), "l"(src));
}
#define CP_COMMIT() asm volatile("cp.async.commit_group;\n" ::: "memory")
#define CP_WAIT1()  asm volatile("cp.async.wait_group 1;\n" ::: "memory")
#define CP_WAIT0()  asm volatile("cp.async.wait_group 0;\n" ::: "memory")

#define LDSM_X4(r0, r1, r2, r3, addr)                                        \
    asm volatile("ldmatrix.sync.aligned.m8n8.x4.shared.b16 {%0,%1,%2,%3}, [%4];" \
                 : "=r"(r0), "=r"(r1), "=r"(r2), "=r"(r3) : "r"(addr))

#define MMA_F16(d, a, b0, b1)                                                \
    asm volatile("mma.sync.aligned.m16n8k16.row.col.f32.f16.f16.f32 "        \
                 "{%0,%1,%2,%3}, {%4,%5,%6,%7}, {%8,%9}, {%0,%1,%2,%3};"     \
                 : "+f"((d)[0]), "+f"((d)[1]), "+f"((d)[2]), "+f"((d)[3])    \
                 : "r"((a)[0]), "r"((a)[1]), "r"((a)[2]), "r"((a)[3]),       \
                   "r"(b0), "r"(b1))

__device__ __forceinline__ uint32_t f2h2(float a, float b) {
    __half2 t = __floats2half2_rn(a, b);
    return *reinterpret_cast<uint32_t*>(&t);
}
// split (a,b) into packed fp16x2 hi and lo
__device__ __forceinline__ void split2h(float a, float b,
                                        uint32_t& hi, uint32_t& lo) {
    float ah = __half2float(__float2half_rn(a));
    float bh = __half2float(__float2half_rn(b));
    hi = f2h2(ah, bh);
    lo = f2h2(a - ah, b - bh);
}

// ---------------------------------------------------------------------------
// Conversion kernels
// ---------------------------------------------------------------------------
__global__ void convert_split_kernel(const float* __restrict__ in,
                                     __half* __restrict__ hi,
                                     __half* __restrict__ lo, int n4)
{
    int i = blockIdx.x * blockDim.x + threadIdx.x;
    if (i >= n4) return;
    float4 x = ((const float4*)in)[i];
    uint32_t h0, l0, h1, l1;
    split2h(x.x, x.y, h0, l0);
    split2h(x.z, x.w, h1, l1);
    ((uint2*)hi)[i] = make_uint2(h0, h1);
    ((uint2*)lo)[i] = make_uint2(l0, l1);
}

// W[K,N] fp32 -> Wt[N,K] fp16 (tiled transpose, single precision-level)
__global__ void convert_w_kernel(const float* __restrict__ W,
                                 __half* __restrict__ out, int K, int N)
{
    __shared__ float t[32][33];
    int n0 = blockIdx.x * 32, k0 = blockIdx.y * 32;
    int tx = threadIdx.x, ty = threadIdx.y;  // 32 x 8
#pragma unroll
    for (int r = 0; r < 4; r++)
        t[ty + r * 8][tx] = W[(size_t)(k0 + ty + r * 8) * N + n0 + tx];
    __syncthreads();
#pragma unroll
    for (int r = 0; r < 4; r++) {
        float x = t[tx][ty + r * 8];
        out[(size_t)(n0 + ty + r * 8) * K + k0 + tx] = __float2half_rn(x);
    }
}

// ---------------------------------------------------------------------------
// mma.sync fp16 split-A GEMM:  C = (Ah+Al)@W + bias,  W single fp16.
// 2 products per fragment pair. CTA tile 128x128, 256 threads (8 warps 64x32),
// 3-stage cp.async pipeline, ONE __syncthreads per K-chunk.
// mode 0: C = fp32 out.  mode 1: QKV -> Qh/Ql (split), K, V^T (single fp16).
// ---------------------------------------------------------------------------
#define KC       32
#define NCH      (GK / KC)           // 64
#define ROWB     80                  // 64B data + 16B pad
#define TILE_B   (128 * ROWB)        // 10240
#define STAGE_B  (3 * TILE_B)        // 30720: Ah, Al, B
#define NSTAGE   3
#define GEMM_SMEM (NSTAGE * STAGE_B) // 92160

__global__ void __launch_bounds__(256, 2) mma_gemm_kernel(
    const __half* __restrict__ Ah, const __half* __restrict__ Al,
    const __half* __restrict__ B,
    const float* __restrict__ bias, float* __restrict__ C, int N, int mode)
{
    extern __shared__ char smem[];
    const uint32_t sb = smem_u32(smem);
    const int tid = threadIdx.x;
    const int wid = tid >> 5, lane = tid & 31;
    const int n0 = blockIdx.x * 128, m0 = blockIdx.y * 128;
    const int wm = (wid & 1) * 64, wn = (wid >> 1) * 32;

    const uint32_t aoff = (uint32_t)(wm + (lane & 15)) * ROWB + ((lane >> 4) << 4);
    const uint32_t boff = (uint32_t)(wn + (lane & 7) + ((lane >> 4) << 3)) * ROWB
                        + (((lane >> 3) & 1) << 4);

    float acc[4][4][4];
#pragma unroll
    for (int mi = 0; mi < 4; mi++)
#pragma unroll
        for (int nj = 0; nj < 4; nj++)
#pragma unroll
            for (int d = 0; d < 4; d++) acc[mi][nj][d] = 0.f;

    auto load_chunk = [&](int c, int buf) {
        const int kk = c * KC;
        const uint32_t st = sb + buf * STAGE_B;
        // Ah, Al tiles (rows at m0), B tile (rows at n0)
#pragma unroll
        for (int i = 0; i < 2; i++) {
            int flat = tid + i * 256;
            int r = flat >> 2, s = (flat & 3) * 16;
            cp_async16(st + r * ROWB + s,
                       (const char*)(Ah + (size_t)(m0 + r) * GK + kk) + s);
        }
#pragma unroll
        for (int i = 0; i < 2; i++) {
            int flat = tid + i * 256;
            int r = flat >> 2, s = (flat & 3) * 16;
            cp_async16(st + TILE_B + r * ROWB + s,
                       (const char*)(Al + (size_t)(m0 + r) * GK + kk) + s);
        }
#pragma unroll
        for (int i = 0; i < 2; i++) {
            int flat = tid + i * 256;
            int r = flat >> 2, s = (flat & 3) * 16;
            cp_async16(st + 2 * TILE_B + r * ROWB + s,
                       (const char*)(B + (size_t)(n0 + r) * GK + kk) + s);
        }
    };

    load_chunk(0, 0); CP_COMMIT();
    load_chunk(1, 1); CP_COMMIT();

    for (int c = 0; c < NCH; c++) {
        const int buf = c % NSTAGE;
        CP_WAIT1();          // chunk c resident
        __syncthreads();     // all warps done reading buf[(c+2)%3] (chunk c-1)
        if (c + 2 < NCH) load_chunk(c + 2, (c + 2) % NSTAGE);
        CP_COMMIT();

        const uint32_t sAh = sb + buf * STAGE_B;
        const uint32_t sAl = sAh + TILE_B;
        const uint32_t sB  = sAh + 2 * TILE_B;
#pragma unroll
        for (int ks = 0; ks < 2; ks++) {
            uint32_t b2[2][4];
#pragma unroll
            for (int p = 0; p < 2; p++)
                LDSM_X4(b2[p][0], b2[p][1], b2[p][2], b2[p][3],
                        sB + boff + p * (16 * ROWB) + ks * 32);
#pragma unroll
            for (int mi = 0; mi < 4; mi++) {
                uint32_t ah4[4], al4[4];
                LDSM_X4(ah4[0], ah4[1], ah4[2], ah4[3],
                        sAh + aoff + mi * (16 * ROWB) + ks * 32);
                LDSM_X4(al4[0], al4[1], al4[2], al4[3],
                        sAl + aoff + mi * (16 * ROWB) + ks * 32);
#pragma unroll
                for (int nj = 0; nj < 4; nj++) {
                    const int p = nj >> 1, e = (nj & 1) * 2;
                    MMA_F16(acc[mi][nj], ah4, b2[p][e], b2[p][e + 1]);
                    MMA_F16(acc[mi][nj], al4, b2[p][e], b2[p][e + 1]);
                }
            }
        }
    }

    // ---- epilogue ----
    const int g = lane >> 2, tg = lane & 3;
#pragma unroll
    for (int mi = 0; mi < 4; mi++) {
#pragma unroll
        for (int half = 0; half < 2; half++) {
            const int m = m0 + wm + mi * 16 + g + half * 8;
            const int bb = m >> 11, s = m & (SEQ - 1);
#pragma unroll
            for (int nj = 0; nj < 4; nj++) {
                const int col = n0 + wn + nj * 8 + tg * 2;
                float v0 = acc[mi][nj][half * 2 + 0] + __ldg(&bias[col]);
                float v1 = acc[mi][nj][half * 2 + 1] + __ldg(&bias[col + 1]);
                if (mode == 0) {
                    *(float2*)(C + (size_t)m * N + col) = make_float2(v0, v1);
                } else {
                    const int part = col >> 11;
                    const int h = (col >> 7) & (NH - 1);
                    const int d0 = col & (HD - 1);
                    const size_t bh = (size_t)bb * NH + h;
                    if (part == 0) {
                        uint32_t hi, lo;
                        split2h(v0, v1, hi, lo);
                        size_t idx = (bh * SEQ + s) * HD + d0;
                        *(uint32_t*)(g_Qh + idx) = hi;
                        *(uint32_t*)(g_Ql + idx) = lo;
                    } else if (part == 1) {
                        size_t idx = (bh * SEQ + s) * HD + d0;
                        *(uint32_t*)(g_K + idx) = f2h2(v0, v1);
                    } else {
                        g_Vt[(bh * HD + d0)     * SEQ + s] = __float2half_rn(v0);
                        g_Vt[(bh * HD + d0 + 1) * SEQ + s] = __float2half_rn(v1);
                    }
                }
            }
        }
    }
}

// ---------------------------------------------------------------------------
// Tensor-core flash attention: causal + ALiBi, fp16 split-A (2-product) mma,
// fp32 online softmax, P fragments built in registers.
// CTA: 128 q-rows, k-tiles of 64. 8 warps (warp = 16 q-rows x full tile).
// Output written as fp16 hi/lo straight into g_Ah/g_Al (proj input).
// ---------------------------------------------------------------------------
#define QSTR 272                       // 128 fp16 + 16B pad
#define VSTR 144                       // 64 fp16 + 16B pad
#define OFF_QL (128 * QSTR)            // 34816
#define OFF_KS (2 * 128 * QSTR)        // 69632: K single, 64 rows
#define OFF_VS (OFF_KS + 64 * QSTR)    // 87040: V^T single, 128 rows
#define ATT_SMEM (OFF_VS + 128 * VSTR) // 105472

__global__ void __launch_bounds__(256, 2) attn_mma_kernel()
{
    extern __shared__ char smc[];
    const uint32_t sb = smem_u32(smc);
    const int tid = threadIdx.x;
    const int wid = tid >> 5, lane = tid & 31;
    const int g = lane >> 2, tg = lane & 3;
    const int qt = blockIdx.x, h = blockIdx.y, b = blockIdx.z;
    const size_t bh = (size_t)b * NH + h;
    const int q0 = qt * 128;
    const int WR = wid * 16;

    const float scale = 1.f / 128.f;
    const float slope = exp2f(-0.5f * (float)(h + 1));

    const uint32_t qbase = sb + (uint32_t)(WR + (lane & 15)) * QSTR + ((lane >> 4) << 4);
    const uint32_t kbase = sb + OFF_KS
        + (uint32_t)((lane & 7) + ((lane >> 4) << 3)) * QSTR + (((lane >> 3) & 1) << 4);
    const uint32_t vbase = sb + OFF_VS
        + (uint32_t)((lane & 7) + ((lane >> 4) << 3)) * VSTR + (((lane >> 3) & 1) << 4);

    // ---- load Q (hi/lo) ----
    {
        const __half* Qh = g_Qh + (bh * SEQ + q0) * HD;
        const __half* Ql = g_Ql + (bh * SEQ + q0) * HD;
#pragma unroll
        for (int i = 0; i < 8; i++) {
            int flat = tid + i * 256;
            int r = flat >> 4, cb = (flat & 15) * 16;
            cp_async16(sb + r * QSTR + cb, (const char*)(Qh + (size_t)r * HD) + cb);
        }
#pragma unroll
        for (int i = 0; i < 8; i++) {
            int flat = tid + i * 256;
            int r = flat >> 4, cb = (flat & 15) * 16;
            cp_async16(sb + OFF_QL + r * QSTR + cb, (const char*)(Ql + (size_t)r * HD) + cb);
        }
        CP_COMMIT();
    }

    float oacc[16][4];
#pragma unroll
    for (int nf = 0; nf < 16; nf++)
#pragma unroll
        for (int d = 0; d < 4; d++) oacc[nf][d] = 0.f;
    float m_run[2] = {-1e30f, -1e30f};
    float l_run[2] = {0.f, 0.f};

    const int nkt = 2 * qt + 2;
    for (int kt = 0; kt < nkt; kt++) {
        const int s0 = kt * 64;
        __syncthreads();

        // K tile (single): 64 rows x 256B
        {
            const __half* K = g_K + (bh * SEQ + s0) * HD;
#pragma unroll
            for (int i = 0; i < 4; i++) {
                int flat = tid + i * 256;
                int r = flat >> 4, cb = (flat & 15) * 16;
                cp_async16(sb + OFF_KS + r * QSTR + cb,
                           (const char*)(K + (size_t)r * HD) + cb);
            }
            CP_COMMIT();
        }
        // V^T tile (single): 128 rows x 128B
        {
            const __half* V = g_Vt + bh * HD * SEQ + s0;
#pragma unroll
            for (int i = 0; i < 4; i++) {
                int flat = tid + i * 256;
                int r = flat >> 3, cb = (flat & 7) * 16;
                cp_async16(sb + OFF_VS + r * VSTR + cb,
                           (const char*)(V + (size_t)r * SEQ) + cb);
            }
            CP_COMMIT();
        }
        CP_WAIT1();
        __syncthreads();

        // ---- S = Q K^T (2 products) ----
        float sacc[8][4];
#pragma unroll
        for (int nf = 0; nf < 8; nf++)
#pragma unroll
            for (int d = 0; d < 4; d++) sacc[nf][d] = 0.f;

#pragma unroll
        for (int ks = 0; ks < 8; ks++) {
            uint32_t ah[4], al[4];
            LDSM_X4(ah[0], ah[1], ah[2], ah[3], qbase + ks * 32);
            LDSM_X4(al[0], al[1], al[2], al[3], qbase + OFF_QL + ks * 32);
#pragma unroll
            for (int j = 0; j < 4; j++) {
                uint32_t km[4];
                LDSM_X4(km[0], km[1], km[2], km[3],
                        kbase + j * (16 * QSTR) + ks * 32);
                MMA_F16(sacc[2 * j],     ah, km[0], km[1]);
                MMA_F16(sacc[2 * j],     al, km[0], km[1]);
                MMA_F16(sacc[2 * j + 1], ah, km[2], km[3]);
                MMA_F16(sacc[2 * j + 1], al, km[2], km[3]);
            }
        }

        // ---- bias + mask + online softmax ----
        const int row0 = q0 + WR + g;
        const int row1 = row0 + 8;
#pragma unroll
        for (int nf = 0; nf < 8; nf++) {
            const int cbase = s0 + nf * 8 + tg * 2;
#pragma unroll
            for (int e = 0; e < 2; e++) {
                const int col = cbase + e;
                float v0 = fmaf(sacc[nf][e], scale, slope * (float)(col - row0));
                float v1 = fmaf(sacc[nf][2 + e], scale, slope * (float)(col - row1));
                sacc[nf][e]     = (col > row0) ? -1e30f : v0;
                sacc[nf][2 + e] = (col > row1) ? -1e30f : v1;
            }
        }
#pragma unroll
        for (int half = 0; half < 2; half++) {
            float mx = -1e30f;
#pragma unroll
            for (int nf = 0; nf < 8; nf++)
                mx = fmaxf(mx, fmaxf(sacc[nf][2 * half], sacc[nf][2 * half + 1]));
            mx = fmaxf(mx, __shfl_xor_sync(0xffffffffu, mx, 1));
            mx = fmaxf(mx, __shfl_xor_sync(0xffffffffu, mx, 2));
            float m_new = fmaxf(m_run[half], mx);
            float alpha = __expf(m_run[half] - m_new);
            float ls = 0.f;
#pragma unroll
            for (int nf = 0; nf < 8; nf++) {
                float p0 = __expf(sacc[nf][2 * half] - m_new);
                float p1 = __expf(sacc[nf][2 * half + 1] - m_new);
                sacc[nf][2 * half] = p0;
                sacc[nf][2 * half + 1] = p1;
                ls += p0 + p1;
            }
            ls += __shfl_xor_sync(0xffffffffu, ls, 1);
            ls += __shfl_xor_sync(0xffffffffu, ls, 2);
            l_run[half] = l_run[half] * alpha + ls;
            m_run[half] = m_new;
#pragma unroll
            for (int nf = 0; nf < 16; nf++) {
                oacc[nf][2 * half] *= alpha;
                oacc[nf][2 * half + 1] *= alpha;
            }
        }

        CP_WAIT0();
        __syncthreads();

        // ---- O += P V (2 products), P fragments from registers ----
#pragma unroll
        for (int ks = 0; ks < 4; ks++) {
            uint32_t aph[4], apl[4];
            {
                split2h(sacc[2 * ks][0],     sacc[2 * ks][1],     aph[0], apl[0]);
                split2h(sacc[2 * ks][2],     sacc[2 * ks][3],     aph[1], apl[1]);
                split2h(sacc[2 * ks + 1][0], sacc[2 * ks + 1][1], aph[2], apl[2]);
                split2h(sacc[2 * ks + 1][2], sacc[2 * ks + 1][3], aph[3], apl[3]);
            }
#pragma unroll
            for (int j = 0; j < 8; j++) {
                uint32_t vm[4];
                LDSM_X4(vm[0], vm[1], vm[2], vm[3],
                        vbase + j * (16 * VSTR) + ks * 32);
                MMA_F16(oacc[2 * j],     aph, vm[0], vm[1]);
                MMA_F16(oacc[2 * j],     apl, vm[0], vm[1]);
                MMA_F16(oacc[2 * j + 1], aph, vm[2], vm[3]);
                MMA_F16(oacc[2 * j + 1], apl, vm[2], vm[3]);
            }
        }
    }

    // ---- normalize + write fp16-split O into g_Ah/g_Al ----
    const float inv0 = 1.f / l_run[0];
    const float inv1 = 1.f / l_run[1];
#pragma unroll
    for (int nf = 0; nf < 16; nf++) {
        const int d0 = nf * 8 + tg * 2;
        {
            const int m = b * SEQ + q0 + WR + g;
            uint32_t hi, lo;
            split2h(oacc[nf][0] * inv0, oacc[nf][1] * inv0, hi, lo);
            size_t idx = (size_t)m * HID + h * HD + d0;
            *(uint32_t*)(g_Ah + idx) = hi;
            *(uint32_t*)(g_Al + idx) = lo;
        }
        {
            const int m = b * SEQ + q0 + WR + g + 8;
            uint32_t hi, lo;
            split2h(oacc[nf][2] * inv1, oacc[nf][3] * inv1, hi, lo);
            size_t idx = (size_t)m * HID + h * HD + d0;
            *(uint32_t*)(g_Ah + idx) = hi;
            *(uint32_t*)(g_Al + idx) = lo;
        }
    }
}

// ---------------------------------------------------------------------------
extern "C" void kernel_launch(void* const* d_in, const int* in_sizes, int n_in,
                              void* d_out, int out_size)
{
    const float* hidden = (const float*)d_in[0];
    const float* w_qkv  = (const float*)d_in[1];
    const float* b_qkv  = (const float*)d_in[2];
    const float* w_proj = (const float*)d_in[3];
    const float* b_proj = (const float*)d_in[4];
    float* out = (float*)d_out;

    void *pAh, *pAl, *pWq, *pWp;
    cudaGetSymbolAddress(&pAh, g_Ah);  cudaGetSymbolAddress(&pAl, g_Al);
    cudaGetSymbolAddress(&pWq, g_Wq);  cudaGetSymbolAddress(&pWp, g_Wp);

    cudaFuncSetAttribute(mma_gemm_kernel, cudaFuncAttributeMaxDynamicSharedMemorySize,
                         GEMM_SMEM);
    cudaFuncSetAttribute(attn_mma_kernel, cudaFuncAttributeMaxDynamicSharedMemorySize,
                         ATT_SMEM);

    // weight conversion (transpose, single fp16)
    convert_w_kernel<<<dim3(3 * HID / 32, HID / 32), dim3(32, 8)>>>(
        w_qkv, (__half*)pWq, HID, 3 * HID);
    convert_w_kernel<<<dim3(HID / 32, HID / 32), dim3(32, 8)>>>(
        w_proj, (__half*)pWp, HID, HID);

    // hidden -> fp16 split (GEMM A input)
    {
        int n4 = MTOT * HID / 4;
        convert_split_kernel<<<(n4 + 255) / 256, 256>>>(
            hidden, (__half*)pAh, (__half*)pAl, n4);
    }

    // QKV GEMM -> Qh/Ql (split), K, V^T (single fp16)
    mma_gemm_kernel<<<dim3(3 * HID / 128, MTOT / 128), 256, GEMM_SMEM>>>(
        (const __half*)pAh, (const __half*)pAl, (const __half*)pWq,
        b_qkv, nullptr, 3 * HID, 1);

    // tensor-core flash attention -> g_Ah/g_Al (fp16 split)
    attn_mma_kernel<<<dim3(SEQ / 128, NH, BATCH), 256, ATT_SMEM>>>();

    // proj GEMM -> out
    mma_gemm_kernel<<<dim3(HID / 128, MTOT / 128), 256, GEMM_SMEM>>>(
        (const __half*)pAh, (const __half*)pAl, (const __half*)pWp,
        b_proj, out, HID, 0);
}

// round 8
// speedup vs baseline: 4.7804x; 1.2661x over previous
#include <cuda_runtime.h>
#include <cuda_fp16.h>
#include <cstdint>

#define NH    16
#define HD    128
#define SEQ   2048
#define BATCH 2
#define HID   2048
#define MTOT  (BATCH * SEQ)   // 4096
#define GK    2048

// ---------------------------------------------------------------------------
// Scratch (__device__ globals — allocation-free)
// ---------------------------------------------------------------------------
__device__ __half g_Q [(size_t)BATCH * NH * SEQ * HD];  // Q single [b,h,s,d]
__device__ __half g_K [(size_t)BATCH * NH * SEQ * HD];  // K single [b,h,s,d]
__device__ __half g_Vt[(size_t)BATCH * NH * HD * SEQ];  // V single [b,h,d,s]

__device__ __half g_Ah[(size_t)MTOT * HID];      // GEMM A hi (hidden / attn-out)
__device__ __half g_Al[(size_t)MTOT * HID];      // GEMM A lo
__device__ __half g_Wq[(size_t)3 * HID * HID];   // w_qkv^T fp16 [N,K]
__device__ __half g_Wp[(size_t)HID * HID];       // w_proj^T fp16 [N,K]

// ---------------------------------------------------------------------------
// helpers
// ---------------------------------------------------------------------------
__device__ __forceinline__ uint32_t smem_u32(const void* p) {
    uint32_t a;
    asm("{ .reg .u64 t; cvta.to.shared.u64 t, %1; cvt.u32.u64 %0, t; }"
        : "=r"(a) : "l"(p));
    return a;
}
__device__ __forceinline__ void cp_async16(uint32_t dst, const void* src) {
    asm volatile("cp.async.cg.shared.global [%0], [%1], 16;\n"
                 :: "r"(dst), "l"(src));
}
#define CP_COMMIT() asm volatile("cp.async.commit_group;\n" ::: "memory")
#define CP_WAIT1()  asm volatile("cp.async.wait_group 1;\n" ::: "memory")
#define CP_WAIT0()  asm volatile("cp.async.wait_group 0;\n" ::: "memory")

#define LDSM_X4(r0, r1, r2, r3, addr)                                        \
    asm volatile("ldmatrix.sync.aligned.m8n8.x4.shared.b16 {%0,%1,%2,%3}, [%4];" \
                 : "=r"(r0), "=r"(r1), "=r"(r2), "=r"(r3) : "r"(addr))

#define MMA_F16(d, a, b0, b1)                                                \
    asm volatile("mma.sync.aligned.m16n8k16.row.col.f32.f16.f16.f32 "        \
                 "{%0,%1,%2,%3}, {%4,%5,%6,%7}, {%8,%9}, {%0,%1,%2,%3};"     \
                 : "+f"((d)[0]), "+f"((d)[1]), "+f"((d)[2]), "+f"((d)[3])    \
                 : "r"((a)[0]), "r"((a)[1]), "r"((a)[2]), "r"((a)[3]),       \
                   "r"(b0), "r"(b1))

__device__ __forceinline__ uint32_t f2h2(float a, float b) {
    __half2 t = __floats2half2_rn(a, b);
    return *reinterpret_cast<uint32_t*>(&t);
}
__device__ __forceinline__ void split2h(float a, float b,
                                        uint32_t& hi, uint32_t& lo) {
    float ah = __half2float(__float2half_rn(a));
    float bh = __half2float(__float2half_rn(b));
    hi = f2h2(ah, bh);
    lo = f2h2(a - ah, b - bh);
}

// ---------------------------------------------------------------------------
// Conversion kernels
// ---------------------------------------------------------------------------
__global__ void convert_split_kernel(const float* __restrict__ in,
                                     __half* __restrict__ hi,
                                     __half* __restrict__ lo, int n4)
{
    int i = blockIdx.x * blockDim.x + threadIdx.x;
    if (i >= n4) return;
    float4 x = ((const float4*)in)[i];
    uint32_t h0, l0, h1, l1;
    split2h(x.x, x.y, h0, l0);
    split2h(x.z, x.w, h1, l1);
    ((uint2*)hi)[i] = make_uint2(h0, h1);
    ((uint2*)lo)[i] = make_uint2(l0, l1);
}

// W[K,N] fp32 -> Wt[N,K] fp16 (tiled transpose)
__global__ void convert_w_kernel(const float* __restrict__ W,
                                 __half* __restrict__ out, int K, int N)
{
    __shared__ float t[32][33];
    int n0 = blockIdx.x * 32, k0 = blockIdx.y * 32;
    int tx = threadIdx.x, ty = threadIdx.y;  // 32 x 8
#pragma unroll
    for (int r = 0; r < 4; r++)
        t[ty + r * 8][tx] = W[(size_t)(k0 + ty + r * 8) * N + n0 + tx];
    __syncthreads();
#pragma unroll
    for (int r = 0; r < 4; r++) {
        float x = t[tx][ty + r * 8];
        out[(size_t)(n0 + ty + r * 8) * K + k0 + tx] = __float2half_rn(x);
    }
}

// ---------------------------------------------------------------------------
// mma.sync fp16 split-A GEMM:  C = (Ah+Al)@W + bias,  W single fp16.
// XOR-swizzled smem (128B rows, col ^= (row&7)<<4) — no padding.
// K-chunk 64, 2-stage cp.async pipeline, correct sync placement:
//   sync -> load(c+1) -> commit -> wait1 -> sync -> compute(c)
// CTA 128x128, 256 threads (8 warps of 64x32).
// mode 0: fp32 C out.  mode 1: QKV -> Q, K, V^T (single fp16).
// ---------------------------------------------------------------------------
#define KC       64
#define NCH      (GK / KC)           // 32
#define TILE_B   (128 * 128)         // 16384 bytes: 128 rows x 128B
#define STAGE_B  (3 * TILE_B)        // 49152: Ah, Al, B
#define GEMM_SMEM (2 * STAGE_B)      // 98304 -> 2 CTAs/SM

__global__ void __launch_bounds__(256, 2) mma_gemm_kernel(
    const __half* __restrict__ Ah, const __half* __restrict__ Al,
    const __half* __restrict__ B,
    const float* __restrict__ bias, float* __restrict__ C, int N, int mode)
{
    extern __shared__ char smem[];
    const uint32_t sb = smem_u32(smem);
    const int tid = threadIdx.x;
    const int wid = tid >> 5, lane = tid & 31;
    const int n0 = blockIdx.x * 128, m0 = blockIdx.y * 128;
    const int wm = (wid & 1) * 64, wn = (wid >> 1) * 32;

    const uint32_t swx = (uint32_t)(lane & 7) << 4;       // lane-constant swizzle
    const uint32_t arow = (uint32_t)(wm + (lane & 15)) * 128;
    const uint32_t acol = ((uint32_t)(lane >> 4) << 4);
    const uint32_t brow = (uint32_t)(wn + (lane & 7) + ((lane >> 4) << 3)) * 128;
    const uint32_t bcol = (((uint32_t)(lane >> 3) & 1) << 4);

    float acc[4][4][4];
#pragma unroll
    for (int mi = 0; mi < 4; mi++)
#pragma unroll
        for (int nj = 0; nj < 4; nj++)
#pragma unroll
            for (int d = 0; d < 4; d++) acc[mi][nj][d] = 0.f;

    auto load_chunk = [&](int c, int buf) {
        const int kk = c * KC;
        const uint32_t st = sb + buf * STAGE_B;
        const __half* srcs[3] = {Ah, Al, B};
#pragma unroll
        for (int t = 0; t < 3; t++) {
            const int row0 = (t < 2) ? m0 : n0;
            const __half* src = srcs[t];
            const uint32_t dst = st + t * TILE_B;
#pragma unroll
            for (int i = 0; i < 4; i++) {
                int flat = tid + i * 256;
                int r = flat >> 3;
                int s = (flat & 7) * 16;
                uint32_t off = (uint32_t)r * 128 + (s ^ ((r & 7) << 4));
                cp_async16(dst + off,
                           (const char*)(src + (size_t)(row0 + r) * GK + kk) + s);
            }
        }
    };

    load_chunk(0, 0); CP_COMMIT();

    for (int c = 0; c < NCH; c++) {
        const int buf = c & 1;
        __syncthreads();                       // chunk c-1 consumers done
        if (c + 1 < NCH) load_chunk(c + 1, buf ^ 1);
        CP_COMMIT();
        CP_WAIT1();                            // own copies of chunk c done
        __syncthreads();                       // all threads' copies visible

        const uint32_t sAh = sb + buf * STAGE_B;
        const uint32_t sAl = sAh + TILE_B;
        const uint32_t sB  = sAh + 2 * TILE_B;
#pragma unroll
        for (int ks = 0; ks < 4; ks++) {
            const uint32_t kc = (uint32_t)ks * 32;
            uint32_t b2[2][4];
#pragma unroll
            for (int p = 0; p < 2; p++)
                LDSM_X4(b2[p][0], b2[p][1], b2[p][2], b2[p][3],
                        sB + brow + p * (16 * 128) + ((bcol + kc) ^ swx));
#pragma unroll
            for (int mi = 0; mi < 4; mi++) {
                uint32_t ah4[4], al4[4];
                const uint32_t ao = arow + mi * (16 * 128) + ((acol + kc) ^ swx);
                LDSM_X4(ah4[0], ah4[1], ah4[2], ah4[3], sAh + ao);
                LDSM_X4(al4[0], al4[1], al4[2], al4[3], sAl + ao);
#pragma unroll
                for (int nj = 0; nj < 4; nj++) {
                    const int p = nj >> 1, e = (nj & 1) * 2;
                    MMA_F16(acc[mi][nj], ah4, b2[p][e], b2[p][e + 1]);
                    MMA_F16(acc[mi][nj], al4, b2[p][e], b2[p][e + 1]);
                }
            }
        }
    }

    // ---- epilogue ----
    const int g = lane >> 2, tg = lane & 3;
#pragma unroll
    for (int mi = 0; mi < 4; mi++) {
#pragma unroll
        for (int half = 0; half < 2; half++) {
            const int m = m0 + wm + mi * 16 + g + half * 8;
            const int bb = m >> 11, s = m & (SEQ - 1);
#pragma unroll
            for (int nj = 0; nj < 4; nj++) {
                const int col = n0 + wn + nj * 8 + tg * 2;
                float v0 = acc[mi][nj][half * 2 + 0] + __ldg(&bias[col]);
                float v1 = acc[mi][nj][half * 2 + 1] + __ldg(&bias[col + 1]);
                if (mode == 0) {
                    *(float2*)(C + (size_t)m * N + col) = make_float2(v0, v1);
                } else {
                    const int part = col >> 11;
                    const int h = (col >> 7) & (NH - 1);
                    const int d0 = col & (HD - 1);
                    const size_t bh = (size_t)bb * NH + h;
                    if (part == 0) {
                        *(uint32_t*)(g_Q + (bh * SEQ + s) * HD + d0) = f2h2(v0, v1);
                    } else if (part == 1) {
                        *(uint32_t*)(g_K + (bh * SEQ + s) * HD + d0) = f2h2(v0, v1);
                    } else {
                        g_Vt[(bh * HD + d0)     * SEQ + s] = __float2half_rn(v0);
                        g_Vt[(bh * HD + d0 + 1) * SEQ + s] = __float2half_rn(v1);
                    }
                }
            }
        }
    }
}

// ---------------------------------------------------------------------------
// Tensor-core flash attention: causal + ALiBi, single-fp16 Q/K/V, split-P
// for the PV product, fp32 online softmax, P fragments built in registers.
// CTA: 128 q-rows, k-tiles of 64. 8 warps (warp = 16 q-rows x full tile).
// Output written as fp16 hi/lo straight into g_Ah/g_Al (proj input).
// ---------------------------------------------------------------------------
#define QSTR 272                       // 128 fp16 + 16B pad
#define VSTR 144                       // 64 fp16 + 16B pad
#define OFF_KS (128 * QSTR)            // 34816: K single, 64 rows
#define OFF_VS (OFF_KS + 64 * QSTR)    // 52224: V^T single, 128 rows
#define ATT_SMEM (OFF_VS + 128 * VSTR) // 70656

__global__ void __launch_bounds__(256, 2) attn_mma_kernel()
{
    extern __shared__ char smc[];
    const uint32_t sb = smem_u32(smc);
    const int tid = threadIdx.x;
    const int wid = tid >> 5, lane = tid & 31;
    const int g = lane >> 2, tg = lane & 3;
    const int qt = blockIdx.x, h = blockIdx.y, b = blockIdx.z;
    const size_t bh = (size_t)b * NH + h;
    const int q0 = qt * 128;
    const int WR = wid * 16;

    const float scale = 1.f / 128.f;
    const float slope = exp2f(-0.5f * (float)(h + 1));

    const uint32_t qbase = sb + (uint32_t)(WR + (lane & 15)) * QSTR + ((lane >> 4) << 4);
    const uint32_t kbase = sb + OFF_KS
        + (uint32_t)((lane & 7) + ((lane >> 4) << 3)) * QSTR + (((lane >> 3) & 1) << 4);
    const uint32_t vbase = sb + OFF_VS
        + (uint32_t)((lane & 7) + ((lane >> 4) << 3)) * VSTR + (((lane >> 3) & 1) << 4);

    // ---- load Q (single) ----
    {
        const __half* Q = g_Q + (bh * SEQ + q0) * HD;
#pragma unroll
        for (int i = 0; i < 8; i++) {
            int flat = tid + i * 256;
            int r = flat >> 4, cb = (flat & 15) * 16;
            cp_async16(sb + r * QSTR + cb, (const char*)(Q + (size_t)r * HD) + cb);
        }
        CP_COMMIT();
    }

    float oacc[16][4];
#pragma unroll
    for (int nf = 0; nf < 16; nf++)
#pragma unroll
        for (int d = 0; d < 4; d++) oacc[nf][d] = 0.f;
    float m_run[2] = {-1e30f, -1e30f};
    float l_run[2] = {0.f, 0.f};

    const int nkt = 2 * qt + 2;
    for (int kt = 0; kt < nkt; kt++) {
        const int s0 = kt * 64;
        __syncthreads();

        // K tile (single): 64 rows x 256B
        {
            const __half* K = g_K + (bh * SEQ + s0) * HD;
#pragma unroll
            for (int i = 0; i < 4; i++) {
                int flat = tid + i * 256;
                int r = flat >> 4, cb = (flat & 15) * 16;
                cp_async16(sb + OFF_KS + r * QSTR + cb,
                           (const char*)(K + (size_t)r * HD) + cb);
            }
            CP_COMMIT();
        }
        // V^T tile (single): 128 rows x 128B
        {
            const __half* V = g_Vt + bh * HD * SEQ + s0;
#pragma unroll
            for (int i = 0; i < 4; i++) {
                int flat = tid + i * 256;
                int r = flat >> 3, cb = (flat & 7) * 16;
                cp_async16(sb + OFF_VS + r * VSTR + cb,
                           (const char*)(V + (size_t)r * SEQ) + cb);
            }
            CP_COMMIT();
        }
        CP_WAIT1();        // K ready (Q too on first iter)
        __syncthreads();

        // ---- S = Q K^T (single product) ----
        float sacc[8][4];
#pragma unroll
        for (int nf = 0; nf < 8; nf++)
#pragma unroll
            for (int d = 0; d < 4; d++) sacc[nf][d] = 0.f;

#pragma unroll
        for (int ks = 0; ks < 8; ks++) {
            uint32_t ah[4];
            LDSM_X4(ah[0], ah[1], ah[2], ah[3], qbase + ks * 32);
#pragma unroll
            for (int j = 0; j < 4; j++) {
                uint32_t km[4];
                LDSM_X4(km[0], km[1], km[2], km[3],
                        kbase + j * (16 * QSTR) + ks * 32);
                MMA_F16(sacc[2 * j],     ah, km[0], km[1]);
                MMA_F16(sacc[2 * j + 1], ah, km[2], km[3]);
            }
        }

        // ---- bias + mask + online softmax ----
        const int row0 = q0 + WR + g;
        const int row1 = row0 + 8;
#pragma unroll
        for (int nf = 0; nf < 8; nf++) {
            const int cbase = s0 + nf * 8 + tg * 2;
#pragma unroll
            for (int e = 0; e < 2; e++) {
                const int col = cbase + e;
                float v0 = fmaf(sacc[nf][e], scale, slope * (float)(col - row0));
                float v1 = fmaf(sacc[nf][2 + e], scale, slope * (float)(col - row1));
                sacc[nf][e]     = (col > row0) ? -1e30f : v0;
                sacc[nf][2 + e] = (col > row1) ? -1e30f : v1;
            }
        }
#pragma unroll
        for (int half = 0; half < 2; half++) {
            float mx = -1e30f;
#pragma unroll
            for (int nf = 0; nf < 8; nf++)
                mx = fmaxf(mx, fmaxf(sacc[nf][2 * half], sacc[nf][2 * half + 1]));
            mx = fmaxf(mx, __shfl_xor_sync(0xffffffffu, mx, 1));
            mx = fmaxf(mx, __shfl_xor_sync(0xffffffffu, mx, 2));
            float m_new = fmaxf(m_run[half], mx);
            float alpha = __expf(m_run[half] - m_new);
            float ls = 0.f;
#pragma unroll
            for (int nf = 0; nf < 8; nf++) {
                float p0 = __expf(sacc[nf][2 * half] - m_new);
                float p1 = __expf(sacc[nf][2 * half + 1] - m_new);
                sacc[nf][2 * half] = p0;
                sacc[nf][2 * half + 1] = p1;
                ls += p0 + p1;
            }
            ls += __shfl_xor_sync(0xffffffffu, ls, 1);
            ls += __shfl_xor_sync(0xffffffffu, ls, 2);
            l_run[half] = l_run[half] * alpha + ls;
            m_run[half] = m_new;
#pragma unroll
            for (int nf = 0; nf < 16; nf++) {
                oacc[nf][2 * half] *= alpha;
                oacc[nf][2 * half + 1] *= alpha;
            }
        }

        CP_WAIT0();        // V ready
        __syncthreads();

        // ---- O += P V (split-P, 2 products) ----
#pragma unroll
        for (int ks = 0; ks < 4; ks++) {
            uint32_t aph[4], apl[4];
            {
                split2h(sacc[2 * ks][0],     sacc[2 * ks][1],     aph[0], apl[0]);
                split2h(sacc[2 * ks][2],     sacc[2 * ks][3],     aph[1], apl[1]);
                split2h(sacc[2 * ks + 1][0], sacc[2 * ks + 1][1], aph[2], apl[2]);
                split2h(sacc[2 * ks + 1][2], sacc[2 * ks + 1][3], aph[3], apl[3]);
            }
#pragma unroll
            for (int j = 0; j < 8; j++) {
                uint32_t vm[4];
                LDSM_X4(vm[0], vm[1], vm[2], vm[3],
                        vbase + j * (16 * VSTR) + ks * 32);
                MMA_F16(oacc[2 * j],     aph, vm[0], vm[1]);
                MMA_F16(oacc[2 * j],     apl, vm[0], vm[1]);
                MMA_F16(oacc[2 * j + 1], aph, vm[2], vm[3]);
                MMA_F16(oacc[2 * j + 1], apl, vm[2], vm[3]);
            }
        }
    }

    // ---- normalize + write fp16-split O into g_Ah/g_Al ----
    const float inv0 = 1.f / l_run[0];
    const float inv1 = 1.f / l_run[1];
#pragma unroll
    for (int nf = 0; nf < 16; nf++) {
        const int d0 = nf * 8 + tg * 2;
        {
            const int m = b * SEQ + q0 + WR + g;
            uint32_t hi, lo;
            split2h(oacc[nf][0] * inv0, oacc[nf][1] * inv0, hi, lo);
            size_t idx = (size_t)m * HID + h * HD + d0;
            *(uint32_t*)(g_Ah + idx) = hi;
            *(uint32_t*)(g_Al + idx) = lo;
        }
        {
            const int m = b * SEQ + q0 + WR + g + 8;
            uint32_t hi, lo;
            split2h(oacc[nf][2] * inv1, oacc[nf][3] * inv1, hi, lo);
            size_t idx = (size_t)m * HID + h * HD + d0;
            *(uint32_t*)(g_Ah + idx) = hi;
            *(uint32_t*)(g_Al + idx) = lo;
        }
    }
}

// ---------------------------------------------------------------------------
extern "C" void kernel_launch(void* const* d_in, const int* in_sizes, int n_in,
                              void* d_out, int out_size)
{
    const float* hidden = (const float*)d_in[0];
    const float* w_qkv  = (const float*)d_in[1];
    const float* b_qkv  = (const float*)d_in[2];
    const float* w_proj = (const float*)d_in[3];
    const float* b_proj = (const float*)d_in[4];
    float* out = (float*)d_out;

    void *pAh, *pAl, *pWq, *pWp;
    cudaGetSymbolAddress(&pAh, g_Ah);  cudaGetSymbolAddress(&pAl, g_Al);
    cudaGetSymbolAddress(&pWq, g_Wq);  cudaGetSymbolAddress(&pWp, g_Wp);

    cudaFuncSetAttribute(mma_gemm_kernel, cudaFuncAttributeMaxDynamicSharedMemorySize,
                         GEMM_SMEM);
    cudaFuncSetAttribute(attn_mma_kernel, cudaFuncAttributeMaxDynamicSharedMemorySize,
                         ATT_SMEM);

    // weight conversion (transpose, single fp16)
    convert_w_kernel<<<dim3(3 * HID / 32, HID / 32), dim3(32, 8)>>>(
        w_qkv, (__half*)pWq, HID, 3 * HID);
    convert_w_kernel<<<dim3(HID / 32, HID / 32), dim3(32, 8)>>>(
        w_proj, (__half*)pWp, HID, HID);

    // hidden -> fp16 split (GEMM A input)
    {
        int n4 = MTOT * HID / 4;
        convert_split_kernel<<<(n4 + 255) / 256, 256>>>(
            hidden, (__half*)pAh, (__half*)pAl, n4);
    }

    // QKV GEMM -> Q, K, V^T (single fp16)
    mma_gemm_kernel<<<dim3(3 * HID / 128, MTOT / 128), 256, GEMM_SMEM>>>(
        (const __half*)pAh, (const __half*)pAl, (const __half*)pWq,
        b_qkv, nullptr, 3 * HID, 1);

    // tensor-core flash attention -> g_Ah/g_Al (fp16 split)
    attn_mma_kernel<<<dim3(SEQ / 128, NH, BATCH), 256, ATT_SMEM>>>();

    // proj GEMM -> out
    mma_gemm_kernel<<<dim3(HID / 128, MTOT / 128), 256, GEMM_SMEM>>>(
        (const __half*)pAh, (const __half*)pAl, (const __half*)pWp,
        b_proj, out, HID, 0);
}

// round 9
// speedup vs baseline: 5.1361x; 1.0744x over previous
#include <cuda_runtime.h>
#include <cuda_fp16.h>
#include <cstdint>

#define NH    16
#define HD    128
#define SEQ   2048
#define BATCH 2
#define HID   2048
#define MTOT  (BATCH * SEQ)   // 4096
#define GK    2048
#define LOG2E 1.4426950408889634f

// ---------------------------------------------------------------------------
// Scratch (__device__ globals — allocation-free)
// ---------------------------------------------------------------------------
__device__ __half g_Q [(size_t)BATCH * NH * SEQ * HD];  // Q single [b,h,s,d]
__device__ __half g_K [(size_t)BATCH * NH * SEQ * HD];  // K single [b,h,s,d]
__device__ __half g_Vt[(size_t)BATCH * NH * HD * SEQ];  // V single [b,h,d,s]

__device__ __half g_Ah[(size_t)MTOT * HID];      // GEMM A hi (hidden / attn-out)
__device__ __half g_Al[(size_t)MTOT * HID];      // GEMM A lo
__device__ __half g_Wq[(size_t)3 * HID * HID];   // w_qkv^T fp16 [N,K]
__device__ __half g_Wp[(size_t)HID * HID];       // w_proj^T fp16 [N,K]

// ---------------------------------------------------------------------------
// helpers
// ---------------------------------------------------------------------------
__device__ __forceinline__ uint32_t smem_u32(const void* p) {
    uint32_t a;
    asm("{ .reg .u64 t; cvta.to.shared.u64 t, %1; cvt.u32.u64 %0, t; }"
        : "=r"(a) : "l"(p));
    return a;
}
__device__ __forceinline__ void cp_async16(uint32_t dst, const void* src) {
    asm volatile("cp.async.cg.shared.global [%0], [%1], 16;\n"
                 :: "r"(dst), "l"(src));
}
#define CP_COMMIT() asm volatile("cp.async.commit_group;\n" ::: "memory")
#define CP_WAIT1()  asm volatile("cp.async.wait_group 1;\n" ::: "memory")
#define CP_WAIT0()  asm volatile("cp.async.wait_group 0;\n" ::: "memory")

#define LDSM_X4(r0, r1, r2, r3, addr)                                        \
    asm volatile("ldmatrix.sync.aligned.m8n8.x4.shared.b16 {%0,%1,%2,%3}, [%4];" \
                 : "=r"(r0), "=r"(r1), "=r"(r2), "=r"(r3) : "r"(addr))

#define MMA_F16(d, a, b0, b1)                                                \
    asm volatile("mma.sync.aligned.m16n8k16.row.col.f32.f16.f16.f32 "        \
                 "{%0,%1,%2,%3}, {%4,%5,%6,%7}, {%8,%9}, {%0,%1,%2,%3};"     \
                 : "+f"((d)[0]), "+f"((d)[1]), "+f"((d)[2]), "+f"((d)[3])    \
                 : "r"((a)[0]), "r"((a)[1]), "r"((a)[2]), "r"((a)[3]),       \
                   "r"(b0), "r"(b1))

__device__ __forceinline__ uint32_t f2h2(float a, float b) {
    __half2 t = __floats2half2_rn(a, b);
    return *reinterpret_cast<uint32_t*>(&t);
}
__device__ __forceinline__ void split2h(float a, float b,
                                        uint32_t& hi, uint32_t& lo) {
    float ah = __half2float(__float2half_rn(a));
    float bh = __half2float(__float2half_rn(b));
    hi = f2h2(ah, bh);
    lo = f2h2(a - ah, b - bh);
}
// two fp16 exp2's in one MUFU op
__device__ __forceinline__ uint32_t ex2h2(float a, float b) {
    uint32_t x = f2h2(a, b), r;
    asm("ex2.approx.f16x2 %0, %1;" : "=r"(r) : "r"(x));
    return r;
}

// ---------------------------------------------------------------------------
// Conversion kernels
// ---------------------------------------------------------------------------
__global__ void convert_split_kernel(const float* __restrict__ in,
                                     __half* __restrict__ hi,
                                     __half* __restrict__ lo, int n4)
{
    int i = blockIdx.x * blockDim.x + threadIdx.x;
    if (i >= n4) return;
    float4 x = ((const float4*)in)[i];
    uint32_t h0, l0, h1, l1;
    split2h(x.x, x.y, h0, l0);
    split2h(x.z, x.w, h1, l1);
    ((uint2*)hi)[i] = make_uint2(h0, h1);
    ((uint2*)lo)[i] = make_uint2(l0, l1);
}

// W[K,N] fp32 -> Wt[N,K] fp16 (tiled transpose)
__global__ void convert_w_kernel(const float* __restrict__ W,
                                 __half* __restrict__ out, int K, int N)
{
    __shared__ float t[32][33];
    int n0 = blockIdx.x * 32, k0 = blockIdx.y * 32;
    int tx = threadIdx.x, ty = threadIdx.y;  // 32 x 8
#pragma unroll
    for (int r = 0; r < 4; r++)
        t[ty + r * 8][tx] = W[(size_t)(k0 + ty + r * 8) * N + n0 + tx];
    __syncthreads();
#pragma unroll
    for (int r = 0; r < 4; r++) {
        float x = t[tx][ty + r * 8];
        out[(size_t)(n0 + ty + r * 8) * K + k0 + tx] = __float2half_rn(x);
    }
}

// ---------------------------------------------------------------------------
// mma.sync fp16 split-A GEMM (unchanged from R8 — tensor 75.5%).
// ---------------------------------------------------------------------------
#define KC       64
#define NCH      (GK / KC)           // 32
#define TILE_B   (128 * 128)         // 16384
#define STAGE_B  (3 * TILE_B)        // 49152: Ah, Al, B
#define GEMM_SMEM (2 * STAGE_B)      // 98304 -> 2 CTAs/SM

__global__ void __launch_bounds__(256, 2) mma_gemm_kernel(
    const __half* __restrict__ Ah, const __half* __restrict__ Al,
    const __half* __restrict__ B,
    const float* __restrict__ bias, float* __restrict__ C, int N, int mode)
{
    extern __shared__ char smem[];
    const uint32_t sb = smem_u32(smem);
    const int tid = threadIdx.x;
    const int wid = tid >> 5, lane = tid & 31;
    const int n0 = blockIdx.x * 128, m0 = blockIdx.y * 128;
    const int wm = (wid & 1) * 64, wn = (wid >> 1) * 32;

    const uint32_t swx = (uint32_t)(lane & 7) << 4;
    const uint32_t arow = (uint32_t)(wm + (lane & 15)) * 128;
    const uint32_t acol = ((uint32_t)(lane >> 4) << 4);
    const uint32_t brow = (uint32_t)(wn + (lane & 7) + ((lane >> 4) << 3)) * 128;
    const uint32_t bcol = (((uint32_t)(lane >> 3) & 1) << 4);

    float acc[4][4][4];
#pragma unroll
    for (int mi = 0; mi < 4; mi++)
#pragma unroll
        for (int nj = 0; nj < 4; nj++)
#pragma unroll
            for (int d = 0; d < 4; d++) acc[mi][nj][d] = 0.f;

    auto load_chunk = [&](int c, int buf) {
        const int kk = c * KC;
        const uint32_t st = sb + buf * STAGE_B;
        const __half* srcs[3] = {Ah, Al, B};
#pragma unroll
        for (int t = 0; t < 3; t++) {
            const int row0 = (t < 2) ? m0 : n0;
            const __half* src = srcs[t];
            const uint32_t dst = st + t * TILE_B;
#pragma unroll
            for (int i = 0; i < 4; i++) {
                int flat = tid + i * 256;
                int r = flat >> 3;
                int s = (flat & 7) * 16;
                uint32_t off = (uint32_t)r * 128 + (s ^ ((r & 7) << 4));
                cp_async16(dst + off,
                           (const char*)(src + (size_t)(row0 + r) * GK + kk) + s);
            }
        }
    };

    load_chunk(0, 0); CP_COMMIT();

    for (int c = 0; c < NCH; c++) {
        const int buf = c & 1;
        __syncthreads();
        if (c + 1 < NCH) load_chunk(c + 1, buf ^ 1);
        CP_COMMIT();
        CP_WAIT1();
        __syncthreads();

        const uint32_t sAh = sb + buf * STAGE_B;
        const uint32_t sAl = sAh + TILE_B;
        const uint32_t sB  = sAh + 2 * TILE_B;
#pragma unroll
        for (int ks = 0; ks < 4; ks++) {
            const uint32_t kc = (uint32_t)ks * 32;
            uint32_t b2[2][4];
#pragma unroll
            for (int p = 0; p < 2; p++)
                LDSM_X4(b2[p][0], b2[p][1], b2[p][2], b2[p][3],
                        sB + brow + p * (16 * 128) + ((bcol + kc) ^ swx));
#pragma unroll
            for (int mi = 0; mi < 4; mi++) {
                uint32_t ah4[4], al4[4];
                const uint32_t ao = arow + mi * (16 * 128) + ((acol + kc) ^ swx);
                LDSM_X4(ah4[0], ah4[1], ah4[2], ah4[3], sAh + ao);
                LDSM_X4(al4[0], al4[1], al4[2], al4[3], sAl + ao);
#pragma unroll
                for (int nj = 0; nj < 4; nj++) {
                    const int p = nj >> 1, e = (nj & 1) * 2;
                    MMA_F16(acc[mi][nj], ah4, b2[p][e], b2[p][e + 1]);
                    MMA_F16(acc[mi][nj], al4, b2[p][e], b2[p][e + 1]);
                }
            }
        }
    }

    // ---- epilogue ----
    const int g = lane >> 2, tg = lane & 3;
#pragma unroll
    for (int mi = 0; mi < 4; mi++) {
#pragma unroll
        for (int half = 0; half < 2; half++) {
            const int m = m0 + wm + mi * 16 + g + half * 8;
            const int bb = m >> 11, s = m & (SEQ - 1);
#pragma unroll
            for (int nj = 0; nj < 4; nj++) {
                const int col = n0 + wn + nj * 8 + tg * 2;
                float v0 = acc[mi][nj][half * 2 + 0] + __ldg(&bias[col]);
                float v1 = acc[mi][nj][half * 2 + 1] + __ldg(&bias[col + 1]);
                if (mode == 0) {
                    *(float2*)(C + (size_t)m * N + col) = make_float2(v0, v1);
                } else {
                    const int part = col >> 11;
                    const int h = (col >> 7) & (NH - 1);
                    const int d0 = col & (HD - 1);
                    const size_t bh = (size_t)bb * NH + h;
                    if (part == 0) {
                        *(uint32_t*)(g_Q + (bh * SEQ + s) * HD + d0) = f2h2(v0, v1);
                    } else if (part == 1) {
                        *(uint32_t*)(g_K + (bh * SEQ + s) * HD + d0) = f2h2(v0, v1);
                    } else {
                        g_Vt[(bh * HD + d0)     * SEQ + s] = __float2half_rn(v0);
                        g_Vt[(bh * HD + d0 + 1) * SEQ + s] = __float2half_rn(v1);
                    }
                }
            }
        }
    }
}

// ---------------------------------------------------------------------------
// Tensor-core flash attention: causal + ALiBi in log2 domain, fp16 P via
// ex2.approx.f16x2, single-product PV, row sums via ones-MMA.
// CTA: 128 q-rows, k-tiles of 64. 8 warps (warp = 16 q-rows x full tile).
// Output written as fp16 hi/lo straight into g_Ah/g_Al (proj input).
// ---------------------------------------------------------------------------
#define QSTR 272                       // 128 fp16 + 16B pad
#define VSTR 144                       // 64 fp16 + 16B pad
#define OFF_KS (128 * QSTR)            // 34816: K single, 64 rows
#define OFF_VS (OFF_KS + 64 * QSTR)    // 52224: V^T single, 128 rows
#define ATT_SMEM (OFF_VS + 128 * VSTR) // 70656
#define ONESH2 0x3C003C00u             // {1.0h, 1.0h}

__global__ void __launch_bounds__(256, 2) attn_mma_kernel()
{
    extern __shared__ char smc[];
    const uint32_t sb = smem_u32(smc);
    const int tid = threadIdx.x;
    const int wid = tid >> 5, lane = tid & 31;
    const int g = lane >> 2, tg = lane & 3;
    const int qt = blockIdx.x, h = blockIdx.y, b = blockIdx.z;
    const size_t bh = (size_t)b * NH + h;
    const int q0 = qt * 128;
    const int WR = wid * 16;

    // log2-domain: p = 2^(s*scale2 + slope2*(col-row) - m)
    const float scale2 = (1.f / 128.f) * LOG2E;
    const float slope2 = exp2f(-0.5f * (float)(h + 1)) * LOG2E;

    const uint32_t qbase = sb + (uint32_t)(WR + (lane & 15)) * QSTR + ((lane >> 4) << 4);
    const uint32_t kbase = sb + OFF_KS
        + (uint32_t)((lane & 7) + ((lane >> 4) << 3)) * QSTR + (((lane >> 3) & 1) << 4);
    const uint32_t vbase = sb + OFF_VS
        + (uint32_t)((lane & 7) + ((lane >> 4) << 3)) * VSTR + (((lane >> 3) & 1) << 4);

    // ---- load Q (single) ----
    {
        const __half* Q = g_Q + (bh * SEQ + q0) * HD;
#pragma unroll
        for (int i = 0; i < 8; i++) {
            int flat = tid + i * 256;
            int r = flat >> 4, cb = (flat & 15) * 16;
            cp_async16(sb + r * QSTR + cb, (const char*)(Q + (size_t)r * HD) + cb);
        }
        CP_COMMIT();
    }

    float oacc[16][4];
#pragma unroll
    for (int nf = 0; nf < 16; nf++)
#pragma unroll
        for (int d = 0; d < 4; d++) oacc[nf][d] = 0.f;
    float lacc[4] = {0.f, 0.f, 0.f, 0.f};   // row sums as an extra MMA column
    float m_run[2] = {-1e30f, -1e30f};

    const int nkt = 2 * qt + 2;
    for (int kt = 0; kt < nkt; kt++) {
        const int s0 = kt * 64;
        __syncthreads();

        {
            const __half* K = g_K + (bh * SEQ + s0) * HD;
#pragma unroll
            for (int i = 0; i < 4; i++) {
                int flat = tid + i * 256;
                int r = flat >> 4, cb = (flat & 15) * 16;
                cp_async16(sb + OFF_KS + r * QSTR + cb,
                           (const char*)(K + (size_t)r * HD) + cb);
            }
            CP_COMMIT();
        }
        {
            const __half* V = g_Vt + bh * HD * SEQ + s0;
#pragma unroll
            for (int i = 0; i < 4; i++) {
                int flat = tid + i * 256;
                int r = flat >> 3, cb = (flat & 7) * 16;
                cp_async16(sb + OFF_VS + r * VSTR + cb,
                           (const char*)(V + (size_t)r * SEQ) + cb);
            }
            CP_COMMIT();
        }
        CP_WAIT1();
        __syncthreads();

        // ---- S = Q K^T ----
        float sacc[8][4];
#pragma unroll
        for (int nf = 0; nf < 8; nf++)
#pragma unroll
            for (int d = 0; d < 4; d++) sacc[nf][d] = 0.f;

#pragma unroll
        for (int ks = 0; ks < 8; ks++) {
            uint32_t ah[4];
            LDSM_X4(ah[0], ah[1], ah[2], ah[3], qbase + ks * 32);
#pragma unroll
            for (int j = 0; j < 4; j++) {
                uint32_t km[4];
                LDSM_X4(km[0], km[1], km[2], km[3],
                        kbase + j * (16 * QSTR) + ks * 32);
                MMA_F16(sacc[2 * j],     ah, km[0], km[1]);
                MMA_F16(sacc[2 * j + 1], ah, km[2], km[3]);
            }
        }

        // ---- bias + mask (log2 domain) ----
        const int row0 = q0 + WR + g;
        const int row1 = row0 + 8;
#pragma unroll
        for (int nf = 0; nf < 8; nf++) {
            const int cbase = s0 + nf * 8 + tg * 2;
#pragma unroll
            for (int e = 0; e < 2; e++) {
                const int col = cbase + e;
                float v0 = fmaf(sacc[nf][e], scale2, slope2 * (float)(col - row0));
                float v1 = fmaf(sacc[nf][2 + e], scale2, slope2 * (float)(col - row1));
                sacc[nf][e]     = (col > row0) ? -1e30f : v0;
                sacc[nf][2 + e] = (col > row1) ? -1e30f : v1;
            }
        }

        // ---- online max + rescale ----
        float m_new[2];
#pragma unroll
        for (int half = 0; half < 2; half++) {
            float mx = -1e30f;
#pragma unroll
            for (int nf = 0; nf < 8; nf++)
                mx = fmaxf(mx, fmaxf(sacc[nf][2 * half], sacc[nf][2 * half + 1]));
            mx = fmaxf(mx, __shfl_xor_sync(0xffffffffu, mx, 1));
            mx = fmaxf(mx, __shfl_xor_sync(0xffffffffu, mx, 2));
            m_new[half] = fmaxf(m_run[half], mx);
            float alpha = exp2f(m_run[half] - m_new[half]);
            m_run[half] = m_new[half];
#pragma unroll
            for (int nf = 0; nf < 16; nf++) {
                oacc[nf][2 * half] *= alpha;
                oacc[nf][2 * half + 1] *= alpha;
            }
            lacc[2 * half]     *= alpha;
            lacc[2 * half + 1] *= alpha;
        }

        // ---- P = exp2(S - m) as fp16x2 fragments (one MUFU per pair) ----
        uint32_t ph[8][2];
#pragma unroll
        for (int nf = 0; nf < 8; nf++) {
            ph[nf][0] = ex2h2(sacc[nf][0] - m_new[0], sacc[nf][1] - m_new[0]);
            ph[nf][1] = ex2h2(sacc[nf][2] - m_new[1], sacc[nf][3] - m_new[1]);
        }

        CP_WAIT0();        // V ready
        __syncthreads();

        // ---- O += P V (single product) + row sums via ones-MMA ----
#pragma unroll
        for (int ks = 0; ks < 4; ks++) {
            uint32_t ap[4] = {ph[2 * ks][0], ph[2 * ks][1],
                              ph[2 * ks + 1][0], ph[2 * ks + 1][1]};
            MMA_F16(lacc, ap, ONESH2, ONESH2);   // l += P @ 1
#pragma unroll
            for (int j = 0; j < 8; j++) {
                uint32_t vm[4];
                LDSM_X4(vm[0], vm[1], vm[2], vm[3],
                        vbase + j * (16 * VSTR) + ks * 32);
                MMA_F16(oacc[2 * j],     ap, vm[0], vm[1]);
                MMA_F16(oacc[2 * j + 1], ap, vm[2], vm[3]);
            }
        }
    }

    // ---- normalize + write fp16-split O into g_Ah/g_Al ----
    const float inv0 = 1.f / lacc[0];
    const float inv1 = 1.f / lacc[2];
#pragma unroll
    for (int nf = 0; nf < 16; nf++) {
        const int d0 = nf * 8 + tg * 2;
        {
            const int m = b * SEQ + q0 + WR + g;
            uint32_t hi, lo;
            split2h(oacc[nf][0] * inv0, oacc[nf][1] * inv0, hi, lo);
            size_t idx = (size_t)m * HID + h * HD + d0;
            *(uint32_t*)(g_Ah + idx) = hi;
            *(uint32_t*)(g_Al + idx) = lo;
        }
        {
            const int m = b * SEQ + q0 + WR + g + 8;
            uint32_t hi, lo;
            split2h(oacc[nf][2] * inv1, oacc[nf][3] * inv1, hi, lo);
            size_t idx = (size_t)m * HID + h * HD + d0;
            *(uint32_t*)(g_Ah + idx) = hi;
            *(uint32_t*)(g_Al + idx) = lo;
        }
    }
}

// ---------------------------------------------------------------------------
extern "C" void kernel_launch(void* const* d_in, const int* in_sizes, int n_in,
                              void* d_out, int out_size)
{
    const float* hidden = (const float*)d_in[0];
    const float* w_qkv  = (const float*)d_in[1];
    const float* b_qkv  = (const float*)d_in[2];
    const float* w_proj = (const float*)d_in[3];
    const float* b_proj = (const float*)d_in[4];
    float* out = (float*)d_out;

    void *pAh, *pAl, *pWq, *pWp;
    cudaGetSymbolAddress(&pAh, g_Ah);  cudaGetSymbolAddress(&pAl, g_Al);
    cudaGetSymbolAddress(&pWq, g_Wq);  cudaGetSymbolAddress(&pWp, g_Wp);

    cudaFuncSetAttribute(mma_gemm_kernel, cudaFuncAttributeMaxDynamicSharedMemorySize,
                         GEMM_SMEM);
    cudaFuncSetAttribute(attn_mma_kernel, cudaFuncAttributeMaxDynamicSharedMemorySize,
                         ATT_SMEM);

    // weight conversion (transpose, single fp16)
    convert_w_kernel<<<dim3(3 * HID / 32, HID / 32), dim3(32, 8)>>>(
        w_qkv, (__half*)pWq, HID, 3 * HID);
    convert_w_kernel<<<dim3(HID / 32, HID / 32), dim3(32, 8)>>>(
        w_proj, (__half*)pWp, HID, HID);

    // hidden -> fp16 split (GEMM A input)
    {
        int n4 = MTOT * HID / 4;
        convert_split_kernel<<<(n4 + 255) / 256, 256>>>(
            hidden, (__half*)pAh, (__half*)pAl, n4);
    }

    // QKV GEMM -> Q, K, V^T (single fp16)
    mma_gemm_kernel<<<dim3(3 * HID / 128, MTOT / 128), 256, GEMM_SMEM>>>(
        (const __half*)pAh, (const __half*)pAl, (const __half*)pWq,
        b_qkv, nullptr, 3 * HID, 1);

    // tensor-core flash attention -> g_Ah/g_Al (fp16 split)
    attn_mma_kernel<<<dim3(SEQ / 128, NH, BATCH), 256, ATT_SMEM>>>();

    // proj GEMM -> out
    mma_gemm_kernel<<<dim3(HID / 128, MTOT / 128), 256, GEMM_SMEM>>>(
        (const __half*)pAh, (const __half*)pAl, (const __half*)pWp,
        b_proj, out, HID, 0);
}

// round 10
// speedup vs baseline: 6.7670x; 1.3175x over previous
#include <cuda_runtime.h>
#include <cuda_fp16.h>
#include <cstdint>

#define NH    16
#define HD    128
#define SEQ   2048
#define BATCH 2
#define HID   2048
#define MTOT  (BATCH * SEQ)   // 4096
#define GK    2048
#define LOG2E 1.4426950408889634f

// ---------------------------------------------------------------------------
// Scratch (__device__ globals — allocation-free)
// ---------------------------------------------------------------------------
__device__ __half g_Q [(size_t)BATCH * NH * SEQ * HD];  // Q single [b,h,s,d]
__device__ __half g_K [(size_t)BATCH * NH * SEQ * HD];  // K single [b,h,s,d]
__device__ __half g_Vt[(size_t)BATCH * NH * HD * SEQ];  // V single [b,h,d,s]

__device__ __half g_Ah[(size_t)MTOT * HID];      // GEMM A hi (hidden / attn-out)
__device__ __half g_Al[(size_t)MTOT * HID];      // GEMM A lo (attn-out only)
__device__ __half g_Wq[(size_t)3 * HID * HID];   // w_qkv^T fp16 [N,K]
__device__ __half g_Wp[(size_t)HID * HID];       // w_proj^T fp16 [N,K]

// ---------------------------------------------------------------------------
// helpers
// ---------------------------------------------------------------------------
__device__ __forceinline__ uint32_t smem_u32(const void* p) {
    uint32_t a;
    asm("{ .reg .u64 t; cvta.to.shared.u64 t, %1; cvt.u32.u64 %0, t; }"
        : "=r"(a) : "l"(p));
    return a;
}
__device__ __forceinline__ void cp_async16(uint32_t dst, const void* src) {
    asm volatile("cp.async.cg.shared.global [%0], [%1], 16;\n"
                 :: "r"(dst), "l"(src));
}
#define CP_COMMIT() asm volatile("cp.async.commit_group;\n" ::: "memory")
#define CP_WAIT1()  asm volatile("cp.async.wait_group 1;\n" ::: "memory")
#define CP_WAIT0()  asm volatile("cp.async.wait_group 0;\n" ::: "memory")

#define LDSM_X4(r0, r1, r2, r3, addr)                                        \
    asm volatile("ldmatrix.sync.aligned.m8n8.x4.shared.b16 {%0,%1,%2,%3}, [%4];" \
                 : "=r"(r0), "=r"(r1), "=r"(r2), "=r"(r3) : "r"(addr))

#define MMA_F16(d, a, b0, b1)                                                \
    asm volatile("mma.sync.aligned.m16n8k16.row.col.f32.f16.f16.f32 "        \
                 "{%0,%1,%2,%3}, {%4,%5,%6,%7}, {%8,%9}, {%0,%1,%2,%3};"     \
                 : "+f"((d)[0]), "+f"((d)[1]), "+f"((d)[2]), "+f"((d)[3])    \
                 : "r"((a)[0]), "r"((a)[1]), "r"((a)[2]), "r"((a)[3]),       \
                   "r"(b0), "r"(b1))

__device__ __forceinline__ uint32_t f2h2(float a, float b) {
    __half2 t = __floats2half2_rn(a, b);
    return *reinterpret_cast<uint32_t*>(&t);
}
__device__ __forceinline__ void split2h(float a, float b,
                                        uint32_t& hi, uint32_t& lo) {
    float ah = __half2float(__float2half_rn(a));
    float bh = __half2float(__float2half_rn(b));
    hi = f2h2(ah, bh);
    lo = f2h2(a - ah, b - bh);
}
__device__ __forceinline__ uint32_t ex2h2(float a, float b) {
    uint32_t x = f2h2(a, b), r;
    asm("ex2.approx.f16x2 %0, %1;" : "=r"(r) : "r"(x));
    return r;
}

// ---------------------------------------------------------------------------
// Conversion kernels
// ---------------------------------------------------------------------------
__global__ void convert_h_kernel(const float* __restrict__ in,
                                 __half* __restrict__ out, int n4)
{
    int i = blockIdx.x * blockDim.x + threadIdx.x;
    if (i >= n4) return;
    float4 x = ((const float4*)in)[i];
    ((uint2*)out)[i] = make_uint2(f2h2(x.x, x.y), f2h2(x.z, x.w));
}

// W[K,N] fp32 -> Wt[N,K] fp16 (tiled transpose)
__global__ void convert_w_kernel(const float* __restrict__ W,
                                 __half* __restrict__ out, int K, int N)
{
    __shared__ float t[32][33];
    int n0 = blockIdx.x * 32, k0 = blockIdx.y * 32;
    int tx = threadIdx.x, ty = threadIdx.y;  // 32 x 8
#pragma unroll
    for (int r = 0; r < 4; r++)
        t[ty + r * 8][tx] = W[(size_t)(k0 + ty + r * 8) * N + n0 + tx];
    __syncthreads();
#pragma unroll
    for (int r = 0; r < 4; r++) {
        float x = t[tx][ty + r * 8];
        out[(size_t)(n0 + ty + r * 8) * K + k0 + tx] = __float2half_rn(x);
    }
}

// ---------------------------------------------------------------------------
// mma.sync fp16 GEMM, templated on SPLIT (split-A 2-product vs single-A).
// XOR-swizzled smem, K-chunk 64, 2-stage cp.async pipeline.
// CTA 128x128, 256 threads (8 warps of 64x32).
// mode 0: fp32 C out.  mode 1: QKV -> Q, K, V^T (single fp16).
// ---------------------------------------------------------------------------
#define KC       64
#define NCH      (GK / KC)           // 32
#define TILE_B   (128 * 128)         // 16384

template<bool SPLIT>
__global__ void __launch_bounds__(256, 2) mma_gemm_kernel(
    const __half* __restrict__ Ah, const __half* __restrict__ Al,
    const __half* __restrict__ B,
    const float* __restrict__ bias, float* __restrict__ C, int N, int mode)
{
    constexpr uint32_t NT = SPLIT ? 3 : 2;       // tiles per stage
    constexpr uint32_t STAGE_B = NT * TILE_B;

    extern __shared__ char smem[];
    const uint32_t sb = smem_u32(smem);
    const int tid = threadIdx.x;
    const int wid = tid >> 5, lane = tid & 31;
    const int n0 = blockIdx.x * 128, m0 = blockIdx.y * 128;
    const int wm = (wid & 1) * 64, wn = (wid >> 1) * 32;

    const uint32_t swx = (uint32_t)(lane & 7) << 4;
    const uint32_t arow = (uint32_t)(wm + (lane & 15)) * 128;
    const uint32_t acol = ((uint32_t)(lane >> 4) << 4);
    const uint32_t brow = (uint32_t)(wn + (lane & 7) + ((lane >> 4) << 3)) * 128;
    const uint32_t bcol = (((uint32_t)(lane >> 3) & 1) << 4);

    float acc[4][4][4];
#pragma unroll
    for (int mi = 0; mi < 4; mi++)
#pragma unroll
        for (int nj = 0; nj < 4; nj++)
#pragma unroll
            for (int d = 0; d < 4; d++) acc[mi][nj][d] = 0.f;

    auto load_chunk = [&](int c, int buf) {
        const int kk = c * KC;
        const uint32_t st = sb + buf * STAGE_B;
        const __half* srcs[3] = {Ah, SPLIT ? Al : B, B};
#pragma unroll
        for (uint32_t t = 0; t < NT; t++) {
            const int row0 = (t < NT - 1) ? m0 : n0;   // last tile is B
            const __half* src = srcs[t + (SPLIT ? 0 : (t == 1 ? 1 : 0))];
            // for SPLIT: {Ah, Al, B}; for !SPLIT: {Ah, B}
            const __half* s2 = SPLIT ? ((t == 0) ? Ah : (t == 1) ? Al : B)
                                     : ((t == 0) ? Ah : B);
            (void)src;
            const uint32_t dst = st + t * TILE_B;
#pragma unroll
            for (int i = 0; i < 4; i++) {
                int flat = tid + i * 256;
                int r = flat >> 3;
                int s = (flat & 7) * 16;
                uint32_t off = (uint32_t)r * 128 + (s ^ ((r & 7) << 4));
                cp_async16(dst + off,
                           (const char*)(s2 + (size_t)(row0 + r) * GK + kk) + s);
            }
        }
    };

    load_chunk(0, 0); CP_COMMIT();

    for (int c = 0; c < NCH; c++) {
        const int buf = c & 1;
        __syncthreads();
        if (c + 1 < NCH) load_chunk(c + 1, buf ^ 1);
        CP_COMMIT();
        CP_WAIT1();
        __syncthreads();

        const uint32_t sAh = sb + buf * STAGE_B;
        const uint32_t sAl = sAh + TILE_B;                 // SPLIT only
        const uint32_t sB  = sAh + (NT - 1) * TILE_B;
#pragma unroll
        for (int ks = 0; ks < 4; ks++) {
            const uint32_t kc = (uint32_t)ks * 32;
            uint32_t b2[2][4];
#pragma unroll
            for (int p = 0; p < 2; p++)
                LDSM_X4(b2[p][0], b2[p][1], b2[p][2], b2[p][3],
                        sB + brow + p * (16 * 128) + ((bcol + kc) ^ swx));
#pragma unroll
            for (int mi = 0; mi < 4; mi++) {
                uint32_t ah4[4];
                const uint32_t ao = arow + mi * (16 * 128) + ((acol + kc) ^ swx);
                LDSM_X4(ah4[0], ah4[1], ah4[2], ah4[3], sAh + ao);
                uint32_t al4[4];
                if (SPLIT) {
                    LDSM_X4(al4[0], al4[1], al4[2], al4[3], sAl + ao);
                }
#pragma unroll
                for (int nj = 0; nj < 4; nj++) {
                    const int p = nj >> 1, e = (nj & 1) * 2;
                    MMA_F16(acc[mi][nj], ah4, b2[p][e], b2[p][e + 1]);
                    if (SPLIT)
                        MMA_F16(acc[mi][nj], al4, b2[p][e], b2[p][e + 1]);
                }
            }
        }
    }

    // ---- epilogue ----
    const int g = lane >> 2, tg = lane & 3;
#pragma unroll
    for (int mi = 0; mi < 4; mi++) {
#pragma unroll
        for (int half = 0; half < 2; half++) {
            const int m = m0 + wm + mi * 16 + g + half * 8;
            const int bb = m >> 11, s = m & (SEQ - 1);
#pragma unroll
            for (int nj = 0; nj < 4; nj++) {
                const int col = n0 + wn + nj * 8 + tg * 2;
                float v0 = acc[mi][nj][half * 2 + 0] + __ldg(&bias[col]);
                float v1 = acc[mi][nj][half * 2 + 1] + __ldg(&bias[col + 1]);
                if (mode == 0) {
                    *(float2*)(C + (size_t)m * N + col) = make_float2(v0, v1);
                } else {
                    const int part = col >> 11;
                    const int h = (col >> 7) & (NH - 1);
                    const int d0 = col & (HD - 1);
                    const size_t bh = (size_t)bb * NH + h;
                    if (part == 0) {
                        *(uint32_t*)(g_Q + (bh * SEQ + s) * HD + d0) = f2h2(v0, v1);
                    } else if (part == 1) {
                        *(uint32_t*)(g_K + (bh * SEQ + s) * HD + d0) = f2h2(v0, v1);
                    } else {
                        g_Vt[(bh * HD + d0)     * SEQ + s] = __float2half_rn(v0);
                        g_Vt[(bh * HD + d0 + 1) * SEQ + s] = __float2half_rn(v1);
                    }
                }
            }
        }
    }
}

// ---------------------------------------------------------------------------
// Tensor-core flash attention: causal + ALiBi in log2 domain, fp16 P via
// ex2.approx.f16x2, single-product PV, row sums via ones-MMA.
// Output written as fp16 hi/lo straight into g_Ah/g_Al (proj input).
// ---------------------------------------------------------------------------
#define QSTR 272
#define VSTR 144
#define OFF_KS (128 * QSTR)
#define OFF_VS (OFF_KS + 64 * QSTR)
#define ATT_SMEM (OFF_VS + 128 * VSTR)
#define ONESH2 0x3C003C00u

__global__ void __launch_bounds__(256, 2) attn_mma_kernel()
{
    extern __shared__ char smc[];
    const uint32_t sb = smem_u32(smc);
    const int tid = threadIdx.x;
    const int wid = tid >> 5, lane = tid & 31;
    const int g = lane >> 2, tg = lane & 3;
    const int qt = blockIdx.x, h = blockIdx.y, b = blockIdx.z;
    const size_t bh = (size_t)b * NH + h;
    const int q0 = qt * 128;
    const int WR = wid * 16;

    const float scale2 = (1.f / 128.f) * LOG2E;
    const float slope2 = exp2f(-0.5f * (float)(h + 1)) * LOG2E;

    const uint32_t qbase = sb + (uint32_t)(WR + (lane & 15)) * QSTR + ((lane >> 4) << 4);
    const uint32_t kbase = sb + OFF_KS
        + (uint32_t)((lane & 7) + ((lane >> 4) << 3)) * QSTR + (((lane >> 3) & 1) << 4);
    const uint32_t vbase = sb + OFF_VS
        + (uint32_t)((lane & 7) + ((lane >> 4) << 3)) * VSTR + (((lane >> 3) & 1) << 4);

    {
        const __half* Q = g_Q + (bh * SEQ + q0) * HD;
#pragma unroll
        for (int i = 0; i < 8; i++) {
            int flat = tid + i * 256;
            int r = flat >> 4, cb = (flat & 15) * 16;
            cp_async16(sb + r * QSTR + cb, (const char*)(Q + (size_t)r * HD) + cb);
        }
        CP_COMMIT();
    }

    float oacc[16][4];
#pragma unroll
    for (int nf = 0; nf < 16; nf++)
#pragma unroll
        for (int d = 0; d < 4; d++) oacc[nf][d] = 0.f;
    float lacc[4] = {0.f, 0.f, 0.f, 0.f};
    float m_run[2] = {-1e30f, -1e30f};

    const int nkt = 2 * qt + 2;
    for (int kt = 0; kt < nkt; kt++) {
        const int s0 = kt * 64;
        __syncthreads();

        {
            const __half* K = g_K + (bh * SEQ + s0) * HD;
#pragma unroll
            for (int i = 0; i < 4; i++) {
                int flat = tid + i * 256;
                int r = flat >> 4, cb = (flat & 15) * 16;
                cp_async16(sb + OFF_KS + r * QSTR + cb,
                           (const char*)(K + (size_t)r * HD) + cb);
            }
            CP_COMMIT();
        }
        {
            const __half* V = g_Vt + bh * HD * SEQ + s0;
#pragma unroll
            for (int i = 0; i < 4; i++) {
                int flat = tid + i * 256;
                int r = flat >> 3, cb = (flat & 7) * 16;
                cp_async16(sb + OFF_VS + r * VSTR + cb,
                           (const char*)(V + (size_t)r * SEQ) + cb);
            }
            CP_COMMIT();
        }
        CP_WAIT1();
        __syncthreads();

        // ---- S = Q K^T ----
        float sacc[8][4];
#pragma unroll
        for (int nf = 0; nf < 8; nf++)
#pragma unroll
            for (int d = 0; d < 4; d++) sacc[nf][d] = 0.f;

#pragma unroll
        for (int ks = 0; ks < 8; ks++) {
            uint32_t ah[4];
            LDSM_X4(ah[0], ah[1], ah[2], ah[3], qbase + ks * 32);
#pragma unroll
            for (int j = 0; j < 4; j++) {
                uint32_t km[4];
                LDSM_X4(km[0], km[1], km[2], km[3],
                        kbase + j * (16 * QSTR) + ks * 32);
                MMA_F16(sacc[2 * j],     ah, km[0], km[1]);
                MMA_F16(sacc[2 * j + 1], ah, km[2], km[3]);
            }
        }

        // ---- bias + mask (log2 domain) ----
        const int row0 = q0 + WR + g;
        const int row1 = row0 + 8;
#pragma unroll
        for (int nf = 0; nf < 8; nf++) {
            const int cbase = s0 + nf * 8 + tg * 2;
#pragma unroll
            for (int e = 0; e < 2; e++) {
                const int col = cbase + e;
                float v0 = fmaf(sacc[nf][e], scale2, slope2 * (float)(col - row0));
                float v1 = fmaf(sacc[nf][2 + e], scale2, slope2 * (float)(col - row1));
                sacc[nf][e]     = (col > row0) ? -1e30f : v0;
                sacc[nf][2 + e] = (col > row1) ? -1e30f : v1;
            }
        }

        // ---- online max + rescale ----
        float m_new[2];
#pragma unroll
        for (int half = 0; half < 2; half++) {
            float mx = -1e30f;
#pragma unroll
            for (int nf = 0; nf < 8; nf++)
                mx = fmaxf(mx, fmaxf(sacc[nf][2 * half], sacc[nf][2 * half + 1]));
            mx = fmaxf(mx, __shfl_xor_sync(0xffffffffu, mx, 1));
            mx = fmaxf(mx, __shfl_xor_sync(0xffffffffu, mx, 2));
            m_new[half] = fmaxf(m_run[half], mx);
            float alpha = exp2f(m_run[half] - m_new[half]);
            m_run[half] = m_new[half];
#pragma unroll
            for (int nf = 0; nf < 16; nf++) {
                oacc[nf][2 * half] *= alpha;
                oacc[nf][2 * half + 1] *= alpha;
            }
            lacc[2 * half]     *= alpha;
            lacc[2 * half + 1] *= alpha;
        }

        // ---- P = exp2(S - m) as fp16x2 fragments ----
        uint32_t ph[8][2];
#pragma unroll
        for (int nf = 0; nf < 8; nf++) {
            ph[nf][0] = ex2h2(sacc[nf][0] - m_new[0], sacc[nf][1] - m_new[0]);
            ph[nf][1] = ex2h2(sacc[nf][2] - m_new[1], sacc[nf][3] - m_new[1]);
        }

        CP_WAIT0();
        __syncthreads();

        // ---- O += P V + row sums via ones-MMA ----
#pragma unroll
        for (int ks = 0; ks < 4; ks++) {
            uint32_t ap[4] = {ph[2 * ks][0], ph[2 * ks][1],
                              ph[2 * ks + 1][0], ph[2 * ks + 1][1]};
            MMA_F16(lacc, ap, ONESH2, ONESH2);
#pragma unroll
            for (int j = 0; j < 8; j++) {
                uint32_t vm[4];
                LDSM_X4(vm[0], vm[1], vm[2], vm[3],
                        vbase + j * (16 * VSTR) + ks * 32);
                MMA_F16(oacc[2 * j],     ap, vm[0], vm[1]);
                MMA_F16(oacc[2 * j + 1], ap, vm[2], vm[3]);
            }
        }
    }

    // ---- normalize + write fp16-split O into g_Ah/g_Al ----
    const float inv0 = 1.f / lacc[0];
    const float inv1 = 1.f / lacc[2];
#pragma unroll
    for (int nf = 0; nf < 16; nf++) {
        const int d0 = nf * 8 + tg * 2;
        {
            const int m = b * SEQ + q0 + WR + g;
            uint32_t hi, lo;
            split2h(oacc[nf][0] * inv0, oacc[nf][1] * inv0, hi, lo);
            size_t idx = (size_t)m * HID + h * HD + d0;
            *(uint32_t*)(g_Ah + idx) = hi;
            *(uint32_t*)(g_Al + idx) = lo;
        }
        {
            const int m = b * SEQ + q0 + WR + g + 8;
            uint32_t hi, lo;
            split2h(oacc[nf][2] * inv1, oacc[nf][3] * inv1, hi, lo);
            size_t idx = (size_t)m * HID + h * HD + d0;
            *(uint32_t*)(g_Ah + idx) = hi;
            *(uint32_t*)(g_Al + idx) = lo;
        }
    }
}

// ---------------------------------------------------------------------------
extern "C" void kernel_launch(void* const* d_in, const int* in_sizes, int n_in,
                              void* d_out, int out_size)
{
    const float* hidden = (const float*)d_in[0];
    const float* w_qkv  = (const float*)d_in[1];
    const float* b_qkv  = (const float*)d_in[2];
    const float* w_proj = (const float*)d_in[3];
    const float* b_proj = (const float*)d_in[4];
    float* out = (float*)d_out;

    void *pAh, *pAl, *pWq, *pWp;
    cudaGetSymbolAddress(&pAh, g_Ah);  cudaGetSymbolAddress(&pAl, g_Al);
    cudaGetSymbolAddress(&pWq, g_Wq);  cudaGetSymbolAddress(&pWp, g_Wp);

    const int SMEM_Q = 2 * 2 * TILE_B;   // single-A: 65536
    const int SMEM_P = 2 * 3 * TILE_B;   // split-A:  98304

    cudaFuncSetAttribute(mma_gemm_kernel<false>,
                         cudaFuncAttributeMaxDynamicSharedMemorySize, SMEM_Q);
    cudaFuncSetAttribute(mma_gemm_kernel<true>,
                         cudaFuncAttributeMaxDynamicSharedMemorySize, SMEM_P);
    cudaFuncSetAttribute(attn_mma_kernel,
                         cudaFuncAttributeMaxDynamicSharedMemorySize, ATT_SMEM);

    // weight conversion (transpose, single fp16)
    convert_w_kernel<<<dim3(3 * HID / 32, HID / 32), dim3(32, 8)>>>(
        w_qkv, (__half*)pWq, HID, 3 * HID);
    convert_w_kernel<<<dim3(HID / 32, HID / 32), dim3(32, 8)>>>(
        w_proj, (__half*)pWp, HID, HID);

    // hidden -> single fp16 (QKV GEMM A input)
    {
        int n4 = MTOT * HID / 4;
        convert_h_kernel<<<(n4 + 255) / 256, 256>>>(hidden, (__half*)pAh, n4);
    }

    // QKV GEMM (single-A) -> Q, K, V^T (fp16)
    mma_gemm_kernel<false><<<dim3(3 * HID / 128, MTOT / 128), 256, SMEM_Q>>>(
        (const __half*)pAh, nullptr, (const __half*)pWq,
        b_qkv, nullptr, 3 * HID, 1);

    // tensor-core flash attention -> g_Ah/g_Al (fp16 split)
    attn_mma_kernel<<<dim3(SEQ / 128, NH, BATCH), 256, ATT_SMEM>>>();

    // proj GEMM (split-A) -> out
    mma_gemm_kernel<true><<<dim3(HID / 128, MTOT / 128), 256, SMEM_P>>>(
        (const __half*)pAh, (const __half*)pAl, (const __half*)pWp,
        b_proj, out, HID, 0);
}